// round 10
// baseline (speedup 1.0000x reference)
#include <cuda_runtime.h>
#include <cuda_bf16.h>
#include <math.h>
#include <stdint.h>

// Problem shape (fixed by the reference)
#define BB 4
#define SS 2048
#define DD 1024
#define HH 16
#define HDIM 64
#define MROWS (BB * SS)          // 8192
#define KDIM 1024

// ---------------------------------------------------------------------------
// Scratch: device globals (no cudaMalloc allowed)
// ---------------------------------------------------------------------------
__device__ __nv_bfloat16 g_xh[(size_t)MROWS * KDIM];
__device__ __nv_bfloat16 g_xl[(size_t)MROWS * KDIM];
__device__ __nv_bfloat16 g_qh[(size_t)MROWS * DD];
__device__ __nv_bfloat16 g_ql[(size_t)MROWS * DD];
__device__ __nv_bfloat16 g_kh[(size_t)MROWS * DD];
__device__ __nv_bfloat16 g_kl[(size_t)MROWS * DD];
__device__ __nv_bfloat16 g_vh[(size_t)MROWS * DD];
__device__ __nv_bfloat16 g_vl[(size_t)MROWS * DD];
__device__ __nv_bfloat16 g_yh[(size_t)MROWS * KDIM];
__device__ __nv_bfloat16 g_yl[(size_t)MROWS * KDIM];
__device__ __nv_bfloat16 g_wah[(size_t)3 * DD * KDIM];   // W_attn^T hi/lo [N,K]
__device__ __nv_bfloat16 g_wal[(size_t)3 * DD * KDIM];
__device__ __nv_bfloat16 g_wph[(size_t)DD * KDIM];       // W_proj^T hi/lo [N,K]
__device__ __nv_bfloat16 g_wpl[(size_t)DD * KDIM];

// ---------------------------------------------------------------------------
// PTX helpers (base ISA only: cp.async / ldmatrix / mma.sync)
// ---------------------------------------------------------------------------
__device__ __forceinline__ uint32_t smem_u32(const void* p) {
    uint32_t a;
    asm("{ .reg .u64 t; cvta.to.shared.u64 t, %1; cvt.u32.u64 %0, t; }"
        : "=r"(a) : "l"(p));
    return a;
}

#define CP16(smem, gptr) \
    asm volatile("cp.async.cg.shared.global [%0], [%1], 16;" :: "r"(smem), "l"(gptr))
#define CP_COMMIT() asm volatile("cp.async.commit_group;" ::: "memory")
#define CP_WAIT(n)  asm volatile("cp.async.wait_group %0;" :: "n"(n) : "memory")

__device__ __forceinline__ void ldsm4(uint32_t* r, uint32_t addr) {
    asm volatile("ldmatrix.sync.aligned.m8n8.x4.shared.b16 {%0,%1,%2,%3}, [%4];"
                 : "=r"(r[0]), "=r"(r[1]), "=r"(r[2]), "=r"(r[3]) : "r"(addr));
}
__device__ __forceinline__ void ldsm4t(uint32_t* r, uint32_t addr) {
    asm volatile("ldmatrix.sync.aligned.m8n8.x4.trans.shared.b16 {%0,%1,%2,%3}, [%4];"
                 : "=r"(r[0]), "=r"(r[1]), "=r"(r[2]), "=r"(r[3]) : "r"(addr));
}

__device__ __forceinline__ void mma16816(float* c, const uint32_t* a, const uint32_t* b) {
    asm volatile(
        "mma.sync.aligned.m16n8k16.row.col.f32.bf16.bf16.f32 "
        "{%0,%1,%2,%3}, {%4,%5,%6,%7}, {%8,%9}, {%0,%1,%2,%3};"
        : "+f"(c[0]), "+f"(c[1]), "+f"(c[2]), "+f"(c[3])
        : "r"(a[0]), "r"(a[1]), "r"(a[2]), "r"(a[3]), "r"(b[0]), "r"(b[1]));
}

__device__ __forceinline__ uint32_t pack_bf2(float a, float b) {
    __nv_bfloat162 t = __floats2bfloat162_rn(a, b);
    return *(uint32_t*)&t;
}

// single-instruction MUFU exp2 (independent of -use_fast_math)
__device__ __forceinline__ float ex2(float x) {
    float r;
    asm("ex2.approx.f32 %0, %1;" : "=f"(r) : "f"(x));
    return r;
}

// ---------------------------------------------------------------------------
// Split fp32 -> bf16 hi + bf16 lo
// ---------------------------------------------------------------------------
__global__ __launch_bounds__(256) void split_kernel(
    const float* __restrict__ in, __nv_bfloat16* __restrict__ hi,
    __nv_bfloat16* __restrict__ lo, int n4)
{
    int i = blockIdx.x * 256 + threadIdx.x;
    if (i >= n4) return;
    float4 v = ((const float4*)in)[i];
    __nv_bfloat16 h0 = __float2bfloat16(v.x), h1 = __float2bfloat16(v.y);
    __nv_bfloat16 h2 = __float2bfloat16(v.z), h3 = __float2bfloat16(v.w);
    __nv_bfloat162* hp = (__nv_bfloat162*)hi;
    __nv_bfloat162* lp = (__nv_bfloat162*)lo;
    hp[2 * i + 0] = __halves2bfloat162(h0, h1);
    hp[2 * i + 1] = __halves2bfloat162(h2, h3);
    lp[2 * i + 0] = __floats2bfloat162_rn(v.x - __bfloat162float(h0),
                                          v.y - __bfloat162float(h1));
    lp[2 * i + 1] = __floats2bfloat162_rn(v.z - __bfloat162float(h2),
                                          v.w - __bfloat162float(h3));
}

// ---------------------------------------------------------------------------
// Transpose + split BOTH weight matrices in one launch.
// ---------------------------------------------------------------------------
__global__ void wsplit_t2(const float* __restrict__ Wa, __nv_bfloat16* __restrict__ bah,
                          __nv_bfloat16* __restrict__ bal,
                          const float* __restrict__ Wp, __nv_bfloat16* __restrict__ bph,
                          __nv_bfloat16* __restrict__ bpl)
{
    __shared__ float t[32][33];
    int bx = blockIdx.x;
    const float* W;
    __nv_bfloat16 *bh, *bl;
    int Nd, n0;
    if (bx < 96) { W = Wa; bh = bah; bl = bal; Nd = 3 * DD; n0 = bx * 32; }
    else         { W = Wp; bh = bph; bl = bpl; Nd = DD;     n0 = (bx - 96) * 32; }
    int k0 = blockIdx.y * 32;
    int tx = threadIdx.x, ty = threadIdx.y;   // block (32, 8)
    for (int r = ty; r < 32; r += 8)
        t[r][tx] = W[(size_t)(k0 + r) * Nd + n0 + tx];
    __syncthreads();
    for (int r = ty; r < 32; r += 8) {
        float v = t[tx][r];
        __nv_bfloat16 h = __float2bfloat16(v);
        bh[(size_t)(n0 + r) * KDIM + k0 + tx] = h;
        bl[(size_t)(n0 + r) * KDIM + k0 + tx] = __float2bfloat16(v - __bfloat162float(h));
    }
}

// ---------------------------------------------------------------------------
// mma.sync bf16x3 GEMM, 2 CTAs/SM (unchanged — best measured)
// ---------------------------------------------------------------------------
#define GBM 128
#define GBN 128
#define GBK 32
#define TILE_BYTES (64 * 128)
#define STAGE_BYTES (4 * TILE_BYTES)
#define NSTAGE 3
#define GEMM_SMEM (NSTAGE * STAGE_BYTES)     // 98304

// q scale: hd^-0.5 * log2(e), so softmax can run in exp2 domain
#define QSCALE (0.125f * 1.4426950408889634f)

__device__ __forceinline__ uint32_t a_addr(uint32_t tb, int m0, int ks, int lane) {
    int row = m0 + (lane & 15);
    int p = row >> 1;
    int chl = ((row & 1) << 2) | (ks << 1) | (lane >> 4);
    return tb + p * 128 + ((chl ^ (p & 7)) << 4);
}
__device__ __forceinline__ uint32_t b_addr(uint32_t tb, int n0, int ks, int lane) {
    int row = n0 + (lane & 7) + ((lane >> 4) << 3);
    int p = row >> 1;
    int chl = ((row & 1) << 2) | (ks << 1) | ((lane >> 3) & 1);
    return tb + p * 128 + ((chl ^ (p & 7)) << 4);
}

__global__ __launch_bounds__(256, 2) void gemm_mma_bf16x3(
    const __nv_bfloat16* __restrict__ Ah, const __nv_bfloat16* __restrict__ Al,
    const __nv_bfloat16* __restrict__ Bh, const __nv_bfloat16* __restrict__ Bl,
    const float* __restrict__ bias, float* __restrict__ C, int Nld, int mode,
    __nv_bfloat16* __restrict__ oqh, __nv_bfloat16* __restrict__ oql,
    __nv_bfloat16* __restrict__ okh, __nv_bfloat16* __restrict__ okl,
    __nv_bfloat16* __restrict__ ovh, __nv_bfloat16* __restrict__ ovl)
{
    extern __shared__ __align__(1024) char smraw[];
    const uint32_t sbase = smem_u32(smraw);
    const int tid = threadIdx.x;
    const int lane = tid & 31;
    const int wid = tid >> 5;
    const int wm = wid & 1;
    const int wn = wid >> 1;
    const int row0 = blockIdx.y * GBM;
    const int col0 = blockIdx.x * GBN;

    const int frow = tid >> 2;
    const int fkc  = tid & 3;
    uint32_t so0, so1;
    {
        int p0 = frow >> 1;
        int c0 = (((frow & 1) << 2) | fkc) ^ (p0 & 7);
        so0 = (uint32_t)(p0 * 128 + c0 * 16);
        int r1 = frow + 64;
        int p1 = r1 >> 1;
        int c1 = (((r1 & 1) << 2) | fkc) ^ (p1 & 7);
        so1 = (uint32_t)(p1 * 128 + c1 * 16);
    }
    const __nv_bfloat16* fs0 = Ah + (size_t)(row0 + frow) * KDIM + fkc * 8;
    const __nv_bfloat16* fs1 = Al + (size_t)(row0 + frow) * KDIM + fkc * 8;
    const __nv_bfloat16* fs2 = Bh + (size_t)(col0 + frow) * KDIM + fkc * 8;
    const __nv_bfloat16* fs3 = Bl + (size_t)(col0 + frow) * KDIM + fkc * 8;
    const size_t rstep = (size_t)64 * KDIM;

    float acc[4][4][4];
#pragma unroll
    for (int mi = 0; mi < 4; mi++)
#pragma unroll
        for (int ni = 0; ni < 4; ni++)
#pragma unroll
            for (int q = 0; q < 4; q++) acc[mi][ni][q] = 0.0f;

    auto fill = [&](int s) {
        uint32_t stg = sbase + s * STAGE_BYTES;
        CP16(stg + so0, fs0);                  CP16(stg + so1, fs0 + rstep);
        CP16(stg + TILE_BYTES + so0, fs1);     CP16(stg + TILE_BYTES + so1, fs1 + rstep);
        CP16(stg + 2 * TILE_BYTES + so0, fs2); CP16(stg + 2 * TILE_BYTES + so1, fs2 + rstep);
        CP16(stg + 3 * TILE_BYTES + so0, fs3); CP16(stg + 3 * TILE_BYTES + so1, fs3 + rstep);
        fs0 += GBK; fs1 += GBK; fs2 += GBK; fs3 += GBK;
        CP_COMMIT();
    };

    fill(0);
    fill(1);

    const int NCH = KDIM / GBK;   // 32
    for (int c = 0; c < NCH; c++) {
        int s = c % 3;
        if (c + 2 < NCH) { CP_WAIT(1); } else { CP_WAIT(0); }
        __syncthreads();
        if (c + 2 < NCH) fill((c + 2) % 3);

        uint32_t st = sbase + s * STAGE_BYTES;
#pragma unroll
        for (int ks = 0; ks < 2; ks++) {
            uint32_t aH[4][4], aL[4][4];
#pragma unroll
            for (int mi = 0; mi < 4; mi++) {
                ldsm4(aH[mi], a_addr(st,              wm * 64 + mi * 16, ks, lane));
                ldsm4(aL[mi], a_addr(st + TILE_BYTES, wm * 64 + mi * 16, ks, lane));
            }
#pragma unroll
            for (int g = 0; g < 2; g++) {
                uint32_t bh[4], bl[4];
                ldsm4(bh, b_addr(st + 2 * TILE_BYTES, wn * 32 + g * 16, ks, lane));
                ldsm4(bl, b_addr(st + 3 * TILE_BYTES, wn * 32 + g * 16, ks, lane));
#pragma unroll
                for (int mi = 0; mi < 4; mi++) {
                    mma16816(acc[mi][2 * g],     aH[mi], &bh[0]);
                    mma16816(acc[mi][2 * g + 1], aH[mi], &bh[2]);
                }
#pragma unroll
                for (int mi = 0; mi < 4; mi++) {
                    mma16816(acc[mi][2 * g],     aH[mi], &bl[0]);
                    mma16816(acc[mi][2 * g + 1], aH[mi], &bl[2]);
                }
#pragma unroll
                for (int mi = 0; mi < 4; mi++) {
                    mma16816(acc[mi][2 * g],     aL[mi], &bh[0]);
                    mma16816(acc[mi][2 * g + 1], aL[mi], &bh[2]);
                }
            }
        }
    }

    const int qr = lane >> 2, qc = lane & 3;
    if (mode == 0) {
#pragma unroll
        for (int mi = 0; mi < 4; mi++)
#pragma unroll
            for (int ni = 0; ni < 4; ni++) {
                int row = row0 + wm * 64 + mi * 16 + qr;
                int col = col0 + wn * 32 + ni * 8 + qc * 2;
                float2 bv = *(const float2*)(bias + col);
                float2 v0, v1;
                v0.x = acc[mi][ni][0] + bv.x;  v0.y = acc[mi][ni][1] + bv.y;
                v1.x = acc[mi][ni][2] + bv.x;  v1.y = acc[mi][ni][3] + bv.y;
                *(float2*)(C + (size_t)row * Nld + col) = v0;
                *(float2*)(C + (size_t)(row + 8) * Nld + col) = v1;
            }
    } else {
        int t = col0 >> 10;
        __nv_bfloat16* oh = (t == 0) ? oqh : (t == 1) ? okh : ovh;
        __nv_bfloat16* ol = (t == 0) ? oql : (t == 1) ? okl : ovl;
        float sc = (t == 0) ? QSCALE : 1.0f;   // q in exp2 domain
#pragma unroll
        for (int mi = 0; mi < 4; mi++)
#pragma unroll
            for (int ni = 0; ni < 4; ni++) {
                int row = row0 + wm * 64 + mi * 16 + qr;
                int gcol = col0 + wn * 32 + ni * 8 + qc * 2;
                int lcol = gcol & 1023;
                float2 bv = *(const float2*)(bias + gcol);
                float x0 = (acc[mi][ni][0] + bv.x) * sc;
                float x1 = (acc[mi][ni][1] + bv.y) * sc;
                float x2 = (acc[mi][ni][2] + bv.x) * sc;
                float x3 = (acc[mi][ni][3] + bv.y) * sc;
                __nv_bfloat16 h0 = __float2bfloat16(x0), h1 = __float2bfloat16(x1);
                __nv_bfloat16 h2 = __float2bfloat16(x2), h3 = __float2bfloat16(x3);
                size_t i0 = (size_t)row * DD + lcol;
                size_t i1 = (size_t)(row + 8) * DD + lcol;
                *(__nv_bfloat162*)(oh + i0) = __halves2bfloat162(h0, h1);
                *(__nv_bfloat162*)(oh + i1) = __halves2bfloat162(h2, h3);
                *(__nv_bfloat162*)(ol + i0) = __floats2bfloat162_rn(
                    x0 - __bfloat162float(h0), x1 - __bfloat162float(h1));
                *(__nv_bfloat162*)(ol + i1) = __floats2bfloat162_rn(
                    x2 - __bfloat162float(h2), x3 - __bfloat162float(h3));
            }
    }
}

// ---------------------------------------------------------------------------
// Flash attention, mma.sync bf16x3, causal — round-6 structure with
// MUFU ex2 softmax + hoisted swizzle address bases.
//
// Swizzle algebra: for both K (fa_b) and V (fa_v) fragments row&7 == lane&7,
// and ((2k + c) ^ e)<<4 == ((k<<5) ^ ((e&6)<<4)) + ((c ^ (e&1))<<4)   (bits
// of 2k and c are disjoint), so each ldmatrix address decomposes into
//   stage_base + per-lane-const + xy[i] + compile-time-immediate,
// with xy[i] = (i<<5) ^ ((lane&6)<<4) computed once per CTA.
// ---------------------------------------------------------------------------
#define ATT_TILE_B 16384
#define ATT_KV_STAGE (4 * ATT_TILE_B)
#define ATT_SMEM (2 * ATT_TILE_B + 2 * ATT_KV_STAGE)   // 163840

__device__ __forceinline__ uint32_t sw128(uint32_t tb, int row, int chunk) {
    return tb + row * 128 + ((chunk ^ (row & 7)) << 4);
}
__device__ __forceinline__ uint32_t fa_a(uint32_t tb, int m0, int ks, int lane) {
    int row = m0 + (lane & 15);
    return sw128(tb, row, ks * 2 + (lane >> 4));
}

__global__ __launch_bounds__(256, 1) void flash_attn_mma(
    const __nv_bfloat16* __restrict__ qh, const __nv_bfloat16* __restrict__ ql,
    const __nv_bfloat16* __restrict__ kh, const __nv_bfloat16* __restrict__ kl,
    const __nv_bfloat16* __restrict__ vh, const __nv_bfloat16* __restrict__ vl,
    __nv_bfloat16* __restrict__ yh, __nv_bfloat16* __restrict__ yl)
{
    extern __shared__ __align__(1024) char smraw[];
    const uint32_t sb = smem_u32(smraw);
    const int qt = blockIdx.x, h = blockIdx.y, b = blockIdx.z;
    const int tid = threadIdx.x, lane = tid & 31, w = tid >> 5;
    const size_t rowbase = (size_t)(b * SS) + qt * 128;
    const int hoff = h * HDIM;

    const uint32_t sQh = sb, sQl = sb + ATT_TILE_B;
    const uint32_t sKV = sb + 2 * ATT_TILE_B;

    // hoisted swizzle components (loop-invariant)
    const uint32_t e6 = (uint32_t)(lane & 6) << 4;
    const uint32_t baseK = ((uint32_t)((lane & 7) + ((lane >> 4) << 3)) << 7)
                         + ((uint32_t)(((lane >> 3) & 1) ^ (lane & 1)) << 4);
    const uint32_t baseV = ((uint32_t)((((lane >> 3) & 1) << 3) + (lane & 7)) << 7)
                         + ((uint32_t)((lane >> 4) ^ (lane & 1)) << 4);
    uint32_t xy[4];
#pragma unroll
    for (int i = 0; i < 4; i++) xy[i] = ((uint32_t)i << 5) ^ e6;

    {
        const __nv_bfloat16* qs[2] = {qh, ql};
        for (int i = tid; i < 2048; i += 256) {
            int t = i >> 10, idx = i & 1023, r = idx >> 3, ch = idx & 7;
            CP16(sw128(t ? sQl : sQh, r, ch),
                 qs[t] + (rowbase + r) * DD + hoff + ch * 8);
        }
        CP_COMMIT();
    }

    const __nv_bfloat16* kvs[4] = {kh, kl, vh, vl};
    auto fillkv = [&](int kt, int s) {
        uint32_t stg = sKV + s * ATT_KV_STAGE;
        size_t kvrow = (size_t)(b * SS) + (size_t)kt * 128;
        for (int i = tid; i < 4096; i += 256) {
            int t = i >> 10, idx = i & 1023, r = idx >> 3, ch = idx & 7;
            CP16(sw128(stg + t * ATT_TILE_B, r, ch),
                 kvs[t] + (kvrow + r) * DD + hoff + ch * 8);
        }
        CP_COMMIT();
    };

    fillkv(0, 0);
    if (qt >= 1) fillkv(1, 1);

    float o[8][4];
#pragma unroll
    for (int i = 0; i < 8; i++)
#pragma unroll
        for (int q = 0; q < 4; q++) o[i][q] = 0.0f;
    float mrow[2] = {-1e30f, -1e30f};
    float lrow[2] = {0.0f, 0.0f};

    uint32_t aQh[4][4], aQl[4][4];
    const int qr = lane >> 2, qc = lane & 3;

    for (int kt = 0; kt <= qt; kt++) {
        int s = kt & 1;
        if (kt + 1 <= qt) { CP_WAIT(1); } else { CP_WAIT(0); }
        __syncthreads();

        if (kt == 0) {
#pragma unroll
            for (int ks = 0; ks < 4; ks++) {
                ldsm4(aQh[ks], fa_a(sQh, w * 16, ks, lane));
                ldsm4(aQl[ks], fa_a(sQl, w * 16, ks, lane));
            }
        }

        uint32_t tKh = sKV + s * ATT_KV_STAGE;
        uint32_t tVh = tKh + 2 * ATT_TILE_B;

        float sfr[16][4];
#pragma unroll
        for (int i = 0; i < 16; i++)
#pragma unroll
            for (int q = 0; q < 4; q++) sfr[i][q] = 0.0f;

#pragma unroll
        for (int ks = 0; ks < 4; ks++) {
            uint32_t kb = tKh + baseK + xy[ks];     // hi tile; lo at +ATT_TILE_B
#pragma unroll
            for (int np = 0; np < 4; np++) {
                int ng0 = 2 * np, ng1 = 2 * np + 1;
                uint32_t bhA[4], blA[4], bhB[4], blB[4];
                ldsm4(bhA, kb + ng0 * 2048);
                ldsm4(blA, kb + ATT_TILE_B + ng0 * 2048);
                ldsm4(bhB, kb + ng1 * 2048);
                ldsm4(blB, kb + ATT_TILE_B + ng1 * 2048);
                mma16816(sfr[2 * ng0],     aQh[ks], &bhA[0]);
                mma16816(sfr[2 * ng0 + 1], aQh[ks], &bhA[2]);
                mma16816(sfr[2 * ng1],     aQh[ks], &bhB[0]);
                mma16816(sfr[2 * ng1 + 1], aQh[ks], &bhB[2]);
                mma16816(sfr[2 * ng0],     aQh[ks], &blA[0]);
                mma16816(sfr[2 * ng0 + 1], aQh[ks], &blA[2]);
                mma16816(sfr[2 * ng1],     aQh[ks], &blB[0]);
                mma16816(sfr[2 * ng1 + 1], aQh[ks], &blB[2]);
                mma16816(sfr[2 * ng0],     aQl[ks], &bhA[0]);
                mma16816(sfr[2 * ng0 + 1], aQl[ks], &bhA[2]);
                mma16816(sfr[2 * ng1],     aQl[ks], &bhB[0]);
                mma16816(sfr[2 * ng1 + 1], aQl[ks], &bhB[2]);
            }
        }

        if (kt == qt) {
            int r0 = w * 16 + qr;
#pragma unroll
            for (int nf = 0; nf < 16; nf++) {
                int c0 = nf * 8 + qc * 2;
                if (c0 > r0)     sfr[nf][0] = -1e30f;
                if (c0 + 1 > r0) sfr[nf][1] = -1e30f;
                if (c0 > r0 + 8)     sfr[nf][2] = -1e30f;
                if (c0 + 1 > r0 + 8) sfr[nf][3] = -1e30f;
            }
        }

        float tm0 = -1e30f, tm1 = -1e30f;
#pragma unroll
        for (int nf = 0; nf < 16; nf++) {
            tm0 = fmaxf(tm0, fmaxf(sfr[nf][0], sfr[nf][1]));
            tm1 = fmaxf(tm1, fmaxf(sfr[nf][2], sfr[nf][3]));
        }
#pragma unroll
        for (int off = 1; off <= 2; off <<= 1) {
            tm0 = fmaxf(tm0, __shfl_xor_sync(0xffffffffu, tm0, off));
            tm1 = fmaxf(tm1, __shfl_xor_sync(0xffffffffu, tm1, off));
        }
        float mn0 = fmaxf(mrow[0], tm0), mn1 = fmaxf(mrow[1], tm1);
        float al0 = ex2(mrow[0] - mn0), al1 = ex2(mrow[1] - mn1);
        mrow[0] = mn0; mrow[1] = mn1;

        float rs0 = 0.0f, rs1 = 0.0f;
#pragma unroll
        for (int nf = 0; nf < 16; nf++) {
            sfr[nf][0] = ex2(sfr[nf][0] - mn0);
            sfr[nf][1] = ex2(sfr[nf][1] - mn0);
            sfr[nf][2] = ex2(sfr[nf][2] - mn1);
            sfr[nf][3] = ex2(sfr[nf][3] - mn1);
            rs0 += sfr[nf][0] + sfr[nf][1];
            rs1 += sfr[nf][2] + sfr[nf][3];
        }
#pragma unroll
        for (int off = 1; off <= 2; off <<= 1) {
            rs0 += __shfl_xor_sync(0xffffffffu, rs0, off);
            rs1 += __shfl_xor_sync(0xffffffffu, rs1, off);
        }
        lrow[0] = lrow[0] * al0 + rs0;
        lrow[1] = lrow[1] * al1 + rs1;
#pragma unroll
        for (int i = 0; i < 8; i++) {
            o[i][0] *= al0; o[i][1] *= al0;
            o[i][2] *= al1; o[i][3] *= al1;
        }

#pragma unroll
        for (int ks = 0; ks < 8; ks++) {
            const float* f0 = sfr[2 * ks];
            const float* f1 = sfr[2 * ks + 1];
            uint32_t phx[4], plx[4];
            phx[0] = pack_bf2(f0[0], f0[1]);
            phx[1] = pack_bf2(f0[2], f0[3]);
            phx[2] = pack_bf2(f1[0], f1[1]);
            phx[3] = pack_bf2(f1[2], f1[3]);
            {
                __nv_bfloat162 h0 = *(__nv_bfloat162*)&phx[0];
                __nv_bfloat162 h1 = *(__nv_bfloat162*)&phx[1];
                __nv_bfloat162 h2 = *(__nv_bfloat162*)&phx[2];
                __nv_bfloat162 h3 = *(__nv_bfloat162*)&phx[3];
                plx[0] = pack_bf2(f0[0] - __bfloat162float(h0.x), f0[1] - __bfloat162float(h0.y));
                plx[1] = pack_bf2(f0[2] - __bfloat162float(h1.x), f0[3] - __bfloat162float(h1.y));
                plx[2] = pack_bf2(f1[0] - __bfloat162float(h2.x), f1[1] - __bfloat162float(h2.y));
                plx[3] = pack_bf2(f1[2] - __bfloat162float(h3.x), f1[3] - __bfloat162float(h3.y));
            }
            uint32_t vb = tVh + baseV + ks * 2048;  // hi tile; lo at +ATT_TILE_B
#pragma unroll
            for (int gp = 0; gp < 2; gp++) {
                int ng0 = 2 * gp, ng1 = 2 * gp + 1;
                uint32_t vhA[4], vlA[4], vhB[4], vlB[4];
                ldsm4t(vhA, vb + xy[ng0]);
                ldsm4t(vlA, vb + ATT_TILE_B + xy[ng0]);
                ldsm4t(vhB, vb + xy[ng1]);
                ldsm4t(vlB, vb + ATT_TILE_B + xy[ng1]);
                mma16816(o[2 * ng0],     phx, &vhA[0]);
                mma16816(o[2 * ng0 + 1], phx, &vhA[2]);
                mma16816(o[2 * ng1],     phx, &vhB[0]);
                mma16816(o[2 * ng1 + 1], phx, &vhB[2]);
                mma16816(o[2 * ng0],     plx, &vhA[0]);
                mma16816(o[2 * ng0 + 1], plx, &vhA[2]);
                mma16816(o[2 * ng1],     plx, &vhB[0]);
                mma16816(o[2 * ng1 + 1], plx, &vhB[2]);
                mma16816(o[2 * ng0],     phx, &vlA[0]);
                mma16816(o[2 * ng0 + 1], phx, &vlA[2]);
                mma16816(o[2 * ng1],     phx, &vlB[0]);
                mma16816(o[2 * ng1 + 1], phx, &vlB[2]);
            }
        }

        __syncthreads();
        if (kt + 2 <= qt) fillkv(kt + 2, s);
    }

    float inv0 = 1.0f / lrow[0];
    float inv1 = 1.0f / lrow[1];
    size_t r0 = rowbase + w * 16 + qr;
#pragma unroll
    for (int i = 0; i < 8; i++) {
        int col = hoff + i * 8 + qc * 2;
        float x0 = o[i][0] * inv0, x1 = o[i][1] * inv0;
        float x2 = o[i][2] * inv1, x3 = o[i][3] * inv1;
        __nv_bfloat16 h0 = __float2bfloat16(x0), h1 = __float2bfloat16(x1);
        __nv_bfloat16 h2 = __float2bfloat16(x2), h3 = __float2bfloat16(x3);
        size_t i0 = r0 * DD + col;
        size_t i1 = (r0 + 8) * DD + col;
        *(__nv_bfloat162*)(yh + i0) = __halves2bfloat162(h0, h1);
        *(__nv_bfloat162*)(yh + i1) = __halves2bfloat162(h2, h3);
        *(__nv_bfloat162*)(yl + i0) = __floats2bfloat162_rn(
            x0 - __bfloat162float(h0), x1 - __bfloat162float(h1));
        *(__nv_bfloat162*)(yl + i1) = __floats2bfloat162_rn(
            x2 - __bfloat162float(h2), x3 - __bfloat162float(h3));
    }
}

// ---------------------------------------------------------------------------
extern "C" void kernel_launch(void* const* d_in, const int* in_sizes, int n_in,
                              void* d_out, int out_size)
{
    const float* x      = (const float*)d_in[0];
    const float* W_attn = (const float*)d_in[1];
    const float* b_attn = (const float*)d_in[2];
    const float* W_proj = (const float*)d_in[3];
    const float* b_proj = (const float*)d_in[4];
    float* out = (float*)d_out;

    __nv_bfloat16 *xh, *xl, *qhp, *qlp, *khp, *klp, *vhp, *vlp, *yhp, *ylp;
    __nv_bfloat16 *wah, *wal, *wph, *wpl;
    cudaGetSymbolAddress((void**)&xh,  g_xh);
    cudaGetSymbolAddress((void**)&xl,  g_xl);
    cudaGetSymbolAddress((void**)&qhp, g_qh);
    cudaGetSymbolAddress((void**)&qlp, g_ql);
    cudaGetSymbolAddress((void**)&khp, g_kh);
    cudaGetSymbolAddress((void**)&klp, g_kl);
    cudaGetSymbolAddress((void**)&vhp, g_vh);
    cudaGetSymbolAddress((void**)&vlp, g_vl);
    cudaGetSymbolAddress((void**)&yhp, g_yh);
    cudaGetSymbolAddress((void**)&ylp, g_yl);
    cudaGetSymbolAddress((void**)&wah, g_wah);
    cudaGetSymbolAddress((void**)&wal, g_wal);
    cudaGetSymbolAddress((void**)&wph, g_wph);
    cudaGetSymbolAddress((void**)&wpl, g_wpl);

    cudaFuncSetAttribute(gemm_mma_bf16x3, cudaFuncAttributeMaxDynamicSharedMemorySize,
                         (int)GEMM_SMEM);
    cudaFuncSetAttribute(flash_attn_mma, cudaFuncAttributeMaxDynamicSharedMemorySize,
                         (int)ATT_SMEM);

    split_kernel<<<(MROWS * KDIM / 4 + 255) / 256, 256>>>(x, xh, xl, MROWS * KDIM / 4);
    wsplit_t2<<<dim3(128, KDIM / 32), dim3(32, 8)>>>(W_attn, wah, wal, W_proj, wph, wpl);

    gemm_mma_bf16x3<<<dim3(3 * DD / GBN, MROWS / GBM), 256, GEMM_SMEM>>>(
        xh, xl, wah, wal, b_attn, nullptr, 3 * DD, 1,
        qhp, qlp, khp, klp, vhp, vlp);

    flash_attn_mma<<<dim3(SS / 128, HH, BB), 256, ATT_SMEM>>>(
        qhp, qlp, khp, klp, vhp, vlp, yhp, ylp);

    gemm_mma_bf16x3<<<dim3(DD / GBN, MROWS / GBM), 256, GEMM_SMEM>>>(
        yhp, ylp, wph, wpl, b_proj, out, DD, 0,
        nullptr, nullptr, nullptr, nullptr, nullptr, nullptr);
}

// round 11
// speedup vs baseline: 1.0237x; 1.0237x over previous
#include <cuda_runtime.h>
#include <cuda_bf16.h>
#include <math.h>
#include <stdint.h>

// Problem shape (fixed by the reference)
#define BB 4
#define SS 2048
#define DD 1024
#define HH 16
#define HDIM 64
#define MROWS (BB * SS)          // 8192
#define KDIM 1024

// ---------------------------------------------------------------------------
// Scratch: device globals (no cudaMalloc allowed)
// ---------------------------------------------------------------------------
__device__ __nv_bfloat16 g_xh[(size_t)MROWS * KDIM];
__device__ __nv_bfloat16 g_xl[(size_t)MROWS * KDIM];
__device__ __nv_bfloat16 g_qh[(size_t)MROWS * DD];
__device__ __nv_bfloat16 g_ql[(size_t)MROWS * DD];
__device__ __nv_bfloat16 g_kh[(size_t)MROWS * DD];
__device__ __nv_bfloat16 g_kl[(size_t)MROWS * DD];
__device__ __nv_bfloat16 g_vh[(size_t)MROWS * DD];
__device__ __nv_bfloat16 g_vl[(size_t)MROWS * DD];
__device__ __nv_bfloat16 g_yh[(size_t)MROWS * KDIM];
__device__ __nv_bfloat16 g_yl[(size_t)MROWS * KDIM];
__device__ __nv_bfloat16 g_wah[(size_t)3 * DD * KDIM];   // W_attn^T hi/lo [N,K]
__device__ __nv_bfloat16 g_wal[(size_t)3 * DD * KDIM];
__device__ __nv_bfloat16 g_wph[(size_t)DD * KDIM];       // W_proj^T hi/lo [N,K]
__device__ __nv_bfloat16 g_wpl[(size_t)DD * KDIM];

// ---------------------------------------------------------------------------
// PTX helpers (base ISA only: cp.async / ldmatrix / mma.sync)
// ---------------------------------------------------------------------------
__device__ __forceinline__ uint32_t smem_u32(const void* p) {
    uint32_t a;
    asm("{ .reg .u64 t; cvta.to.shared.u64 t, %1; cvt.u32.u64 %0, t; }"
        : "=r"(a) : "l"(p));
    return a;
}

#define CP16(smem, gptr) \
    asm volatile("cp.async.cg.shared.global [%0], [%1], 16;" :: "r"(smem), "l"(gptr))
#define CP_COMMIT() asm volatile("cp.async.commit_group;" ::: "memory")
#define CP_WAIT(n)  asm volatile("cp.async.wait_group %0;" :: "n"(n) : "memory")

__device__ __forceinline__ void ldsm4(uint32_t* r, uint32_t addr) {
    asm volatile("ldmatrix.sync.aligned.m8n8.x4.shared.b16 {%0,%1,%2,%3}, [%4];"
                 : "=r"(r[0]), "=r"(r[1]), "=r"(r[2]), "=r"(r[3]) : "r"(addr));
}
__device__ __forceinline__ void ldsm4t(uint32_t* r, uint32_t addr) {
    asm volatile("ldmatrix.sync.aligned.m8n8.x4.trans.shared.b16 {%0,%1,%2,%3}, [%4];"
                 : "=r"(r[0]), "=r"(r[1]), "=r"(r[2]), "=r"(r[3]) : "r"(addr));
}

__device__ __forceinline__ void mma16816(float* c, const uint32_t* a, const uint32_t* b) {
    asm volatile(
        "mma.sync.aligned.m16n8k16.row.col.f32.bf16.bf16.f32 "
        "{%0,%1,%2,%3}, {%4,%5,%6,%7}, {%8,%9}, {%0,%1,%2,%3};"
        : "+f"(c[0]), "+f"(c[1]), "+f"(c[2]), "+f"(c[3])
        : "r"(a[0]), "r"(a[1]), "r"(a[2]), "r"(a[3]), "r"(b[0]), "r"(b[1]));
}

__device__ __forceinline__ uint32_t pack_bf2(float a, float b) {
    __nv_bfloat162 t = __floats2bfloat162_rn(a, b);
    return *(uint32_t*)&t;
}

// ---------------------------------------------------------------------------
// Split fp32 -> bf16 hi + bf16 lo
// ---------------------------------------------------------------------------
__global__ __launch_bounds__(256) void split_kernel(
    const float* __restrict__ in, __nv_bfloat16* __restrict__ hi,
    __nv_bfloat16* __restrict__ lo, int n4)
{
    int i = blockIdx.x * 256 + threadIdx.x;
    if (i >= n4) return;
    float4 v = ((const float4*)in)[i];
    __nv_bfloat16 h0 = __float2bfloat16(v.x), h1 = __float2bfloat16(v.y);
    __nv_bfloat16 h2 = __float2bfloat16(v.z), h3 = __float2bfloat16(v.w);
    __nv_bfloat162* hp = (__nv_bfloat162*)hi;
    __nv_bfloat162* lp = (__nv_bfloat162*)lo;
    hp[2 * i + 0] = __halves2bfloat162(h0, h1);
    hp[2 * i + 1] = __halves2bfloat162(h2, h3);
    lp[2 * i + 0] = __floats2bfloat162_rn(v.x - __bfloat162float(h0),
                                          v.y - __bfloat162float(h1));
    lp[2 * i + 1] = __floats2bfloat162_rn(v.z - __bfloat162float(h2),
                                          v.w - __bfloat162float(h3));
}

// ---------------------------------------------------------------------------
// Transpose + split BOTH weight matrices in one launch.
// ---------------------------------------------------------------------------
__global__ void wsplit_t2(const float* __restrict__ Wa, __nv_bfloat16* __restrict__ bah,
                          __nv_bfloat16* __restrict__ bal,
                          const float* __restrict__ Wp, __nv_bfloat16* __restrict__ bph,
                          __nv_bfloat16* __restrict__ bpl)
{
    __shared__ float t[32][33];
    int bx = blockIdx.x;
    const float* W;
    __nv_bfloat16 *bh, *bl;
    int Nd, n0;
    if (bx < 96) { W = Wa; bh = bah; bl = bal; Nd = 3 * DD; n0 = bx * 32; }
    else         { W = Wp; bh = bph; bl = bpl; Nd = DD;     n0 = (bx - 96) * 32; }
    int k0 = blockIdx.y * 32;
    int tx = threadIdx.x, ty = threadIdx.y;   // block (32, 8)
    for (int r = ty; r < 32; r += 8)
        t[r][tx] = W[(size_t)(k0 + r) * Nd + n0 + tx];
    __syncthreads();
    for (int r = ty; r < 32; r += 8) {
        float v = t[tx][r];
        __nv_bfloat16 h = __float2bfloat16(v);
        bh[(size_t)(n0 + r) * KDIM + k0 + tx] = h;
        bl[(size_t)(n0 + r) * KDIM + k0 + tx] = __float2bfloat16(v - __bfloat162float(h));
    }
}

// ---------------------------------------------------------------------------
// mma.sync bf16x3 GEMM, 2 CTAs/SM (unchanged — best measured)
// ---------------------------------------------------------------------------
#define GBM 128
#define GBN 128
#define GBK 32
#define TILE_BYTES (64 * 128)
#define STAGE_BYTES (4 * TILE_BYTES)
#define NSTAGE 3
#define GEMM_SMEM (NSTAGE * STAGE_BYTES)     // 98304

// q scale: hd^-0.5 * log2(e), so softmax can run in exp2 domain
#define QSCALE (0.125f * 1.4426950408889634f)

__device__ __forceinline__ uint32_t a_addr(uint32_t tb, int m0, int ks, int lane) {
    int row = m0 + (lane & 15);
    int p = row >> 1;
    int chl = ((row & 1) << 2) | (ks << 1) | (lane >> 4);
    return tb + p * 128 + ((chl ^ (p & 7)) << 4);
}
__device__ __forceinline__ uint32_t b_addr(uint32_t tb, int n0, int ks, int lane) {
    int row = n0 + (lane & 7) + ((lane >> 4) << 3);
    int p = row >> 1;
    int chl = ((row & 1) << 2) | (ks << 1) | ((lane >> 3) & 1);
    return tb + p * 128 + ((chl ^ (p & 7)) << 4);
}

__global__ __launch_bounds__(256, 2) void gemm_mma_bf16x3(
    const __nv_bfloat16* __restrict__ Ah, const __nv_bfloat16* __restrict__ Al,
    const __nv_bfloat16* __restrict__ Bh, const __nv_bfloat16* __restrict__ Bl,
    const float* __restrict__ bias, float* __restrict__ C, int Nld, int mode,
    __nv_bfloat16* __restrict__ oqh, __nv_bfloat16* __restrict__ oql,
    __nv_bfloat16* __restrict__ okh, __nv_bfloat16* __restrict__ okl,
    __nv_bfloat16* __restrict__ ovh, __nv_bfloat16* __restrict__ ovl)
{
    extern __shared__ __align__(1024) char smraw[];
    const uint32_t sbase = smem_u32(smraw);
    const int tid = threadIdx.x;
    const int lane = tid & 31;
    const int wid = tid >> 5;
    const int wm = wid & 1;
    const int wn = wid >> 1;
    const int row0 = blockIdx.y * GBM;
    const int col0 = blockIdx.x * GBN;

    const int frow = tid >> 2;
    const int fkc  = tid & 3;
    uint32_t so0, so1;
    {
        int p0 = frow >> 1;
        int c0 = (((frow & 1) << 2) | fkc) ^ (p0 & 7);
        so0 = (uint32_t)(p0 * 128 + c0 * 16);
        int r1 = frow + 64;
        int p1 = r1 >> 1;
        int c1 = (((r1 & 1) << 2) | fkc) ^ (p1 & 7);
        so1 = (uint32_t)(p1 * 128 + c1 * 16);
    }
    const __nv_bfloat16* fs0 = Ah + (size_t)(row0 + frow) * KDIM + fkc * 8;
    const __nv_bfloat16* fs1 = Al + (size_t)(row0 + frow) * KDIM + fkc * 8;
    const __nv_bfloat16* fs2 = Bh + (size_t)(col0 + frow) * KDIM + fkc * 8;
    const __nv_bfloat16* fs3 = Bl + (size_t)(col0 + frow) * KDIM + fkc * 8;
    const size_t rstep = (size_t)64 * KDIM;

    float acc[4][4][4];
#pragma unroll
    for (int mi = 0; mi < 4; mi++)
#pragma unroll
        for (int ni = 0; ni < 4; ni++)
#pragma unroll
            for (int q = 0; q < 4; q++) acc[mi][ni][q] = 0.0f;

    auto fill = [&](int s) {
        uint32_t stg = sbase + s * STAGE_BYTES;
        CP16(stg + so0, fs0);                  CP16(stg + so1, fs0 + rstep);
        CP16(stg + TILE_BYTES + so0, fs1);     CP16(stg + TILE_BYTES + so1, fs1 + rstep);
        CP16(stg + 2 * TILE_BYTES + so0, fs2); CP16(stg + 2 * TILE_BYTES + so1, fs2 + rstep);
        CP16(stg + 3 * TILE_BYTES + so0, fs3); CP16(stg + 3 * TILE_BYTES + so1, fs3 + rstep);
        fs0 += GBK; fs1 += GBK; fs2 += GBK; fs3 += GBK;
        CP_COMMIT();
    };

    fill(0);
    fill(1);

    const int NCH = KDIM / GBK;   // 32
    for (int c = 0; c < NCH; c++) {
        int s = c % 3;
        if (c + 2 < NCH) { CP_WAIT(1); } else { CP_WAIT(0); }
        __syncthreads();
        if (c + 2 < NCH) fill((c + 2) % 3);

        uint32_t st = sbase + s * STAGE_BYTES;
#pragma unroll
        for (int ks = 0; ks < 2; ks++) {
            uint32_t aH[4][4], aL[4][4];
#pragma unroll
            for (int mi = 0; mi < 4; mi++) {
                ldsm4(aH[mi], a_addr(st,              wm * 64 + mi * 16, ks, lane));
                ldsm4(aL[mi], a_addr(st + TILE_BYTES, wm * 64 + mi * 16, ks, lane));
            }
#pragma unroll
            for (int g = 0; g < 2; g++) {
                uint32_t bh[4], bl[4];
                ldsm4(bh, b_addr(st + 2 * TILE_BYTES, wn * 32 + g * 16, ks, lane));
                ldsm4(bl, b_addr(st + 3 * TILE_BYTES, wn * 32 + g * 16, ks, lane));
#pragma unroll
                for (int mi = 0; mi < 4; mi++) {
                    mma16816(acc[mi][2 * g],     aH[mi], &bh[0]);
                    mma16816(acc[mi][2 * g + 1], aH[mi], &bh[2]);
                }
#pragma unroll
                for (int mi = 0; mi < 4; mi++) {
                    mma16816(acc[mi][2 * g],     aH[mi], &bl[0]);
                    mma16816(acc[mi][2 * g + 1], aH[mi], &bl[2]);
                }
#pragma unroll
                for (int mi = 0; mi < 4; mi++) {
                    mma16816(acc[mi][2 * g],     aL[mi], &bh[0]);
                    mma16816(acc[mi][2 * g + 1], aL[mi], &bh[2]);
                }
            }
        }
    }

    const int qr = lane >> 2, qc = lane & 3;
    if (mode == 0) {
#pragma unroll
        for (int mi = 0; mi < 4; mi++)
#pragma unroll
            for (int ni = 0; ni < 4; ni++) {
                int row = row0 + wm * 64 + mi * 16 + qr;
                int col = col0 + wn * 32 + ni * 8 + qc * 2;
                float2 bv = *(const float2*)(bias + col);
                float2 v0, v1;
                v0.x = acc[mi][ni][0] + bv.x;  v0.y = acc[mi][ni][1] + bv.y;
                v1.x = acc[mi][ni][2] + bv.x;  v1.y = acc[mi][ni][3] + bv.y;
                *(float2*)(C + (size_t)row * Nld + col) = v0;
                *(float2*)(C + (size_t)(row + 8) * Nld + col) = v1;
            }
    } else {
        int t = col0 >> 10;
        __nv_bfloat16* oh = (t == 0) ? oqh : (t == 1) ? okh : ovh;
        __nv_bfloat16* ol = (t == 0) ? oql : (t == 1) ? okl : ovl;
        float sc = (t == 0) ? QSCALE : 1.0f;   // q in exp2 domain
#pragma unroll
        for (int mi = 0; mi < 4; mi++)
#pragma unroll
            for (int ni = 0; ni < 4; ni++) {
                int row = row0 + wm * 64 + mi * 16 + qr;
                int gcol = col0 + wn * 32 + ni * 8 + qc * 2;
                int lcol = gcol & 1023;
                float2 bv = *(const float2*)(bias + gcol);
                float x0 = (acc[mi][ni][0] + bv.x) * sc;
                float x1 = (acc[mi][ni][1] + bv.y) * sc;
                float x2 = (acc[mi][ni][2] + bv.x) * sc;
                float x3 = (acc[mi][ni][3] + bv.y) * sc;
                __nv_bfloat16 h0 = __float2bfloat16(x0), h1 = __float2bfloat16(x1);
                __nv_bfloat16 h2 = __float2bfloat16(x2), h3 = __float2bfloat16(x3);
                size_t i0 = (size_t)row * DD + lcol;
                size_t i1 = (size_t)(row + 8) * DD + lcol;
                *(__nv_bfloat162*)(oh + i0) = __halves2bfloat162(h0, h1);
                *(__nv_bfloat162*)(oh + i1) = __halves2bfloat162(h2, h3);
                *(__nv_bfloat162*)(ol + i0) = __floats2bfloat162_rn(
                    x0 - __bfloat162float(h0), x1 - __bfloat162float(h1));
                *(__nv_bfloat162*)(ol + i1) = __floats2bfloat162_rn(
                    x2 - __bfloat162float(h2), x3 - __bfloat162float(h3));
            }
    }
}

// ---------------------------------------------------------------------------
// Flash attention, mma.sync bf16x3, causal — R9 structure with the softmax/PV
// region software-pipelined per ks-group so MUFU exp work overlaps PV tensor
// work. rs shuffle-reduce and lrow update deferred off the critical path.
// ---------------------------------------------------------------------------
#define ATT_TILE_B 16384
#define ATT_KV_STAGE (4 * ATT_TILE_B)
#define ATT_SMEM (2 * ATT_TILE_B + 2 * ATT_KV_STAGE)   // 163840

__device__ __forceinline__ uint32_t sw128(uint32_t tb, int row, int chunk) {
    return tb + row * 128 + ((chunk ^ (row & 7)) << 4);
}
__device__ __forceinline__ uint32_t fa_a(uint32_t tb, int m0, int ks, int lane) {
    int row = m0 + (lane & 15);
    return sw128(tb, row, ks * 2 + (lane >> 4));
}
__device__ __forceinline__ uint32_t fa_b(uint32_t tb, int n0, int ks, int lane) {
    int row = n0 + (lane & 7) + ((lane >> 4) << 3);
    return sw128(tb, row, ks * 2 + ((lane >> 3) & 1));
}
__device__ __forceinline__ uint32_t fa_v(uint32_t tb, int kv0, int hd0, int lane) {
    int row = kv0 + (((lane >> 3) & 1) << 3) + (lane & 7);
    return sw128(tb, row, (hd0 >> 3) + (lane >> 4));
}

__global__ __launch_bounds__(256, 1) void flash_attn_mma(
    const __nv_bfloat16* __restrict__ qh, const __nv_bfloat16* __restrict__ ql,
    const __nv_bfloat16* __restrict__ kh, const __nv_bfloat16* __restrict__ kl,
    const __nv_bfloat16* __restrict__ vh, const __nv_bfloat16* __restrict__ vl,
    __nv_bfloat16* __restrict__ yh, __nv_bfloat16* __restrict__ yl)
{
    extern __shared__ __align__(1024) char smraw[];
    const uint32_t sb = smem_u32(smraw);
    const int qt = blockIdx.x, h = blockIdx.y, b = blockIdx.z;
    const int tid = threadIdx.x, lane = tid & 31, w = tid >> 5;
    const size_t rowbase = (size_t)(b * SS) + qt * 128;
    const int hoff = h * HDIM;

    const uint32_t sQh = sb, sQl = sb + ATT_TILE_B;
    const uint32_t sKV = sb + 2 * ATT_TILE_B;

    {
        const __nv_bfloat16* qs[2] = {qh, ql};
        for (int i = tid; i < 2048; i += 256) {
            int t = i >> 10, idx = i & 1023, r = idx >> 3, ch = idx & 7;
            CP16(sw128(t ? sQl : sQh, r, ch),
                 qs[t] + (rowbase + r) * DD + hoff + ch * 8);
        }
        CP_COMMIT();
    }

    const __nv_bfloat16* kvs[4] = {kh, kl, vh, vl};
    auto fillkv = [&](int kt, int s) {
        uint32_t stg = sKV + s * ATT_KV_STAGE;
        size_t kvrow = (size_t)(b * SS) + (size_t)kt * 128;
        for (int i = tid; i < 4096; i += 256) {
            int t = i >> 10, idx = i & 1023, r = idx >> 3, ch = idx & 7;
            CP16(sw128(stg + t * ATT_TILE_B, r, ch),
                 kvs[t] + (kvrow + r) * DD + hoff + ch * 8);
        }
        CP_COMMIT();
    };

    fillkv(0, 0);
    if (qt >= 1) fillkv(1, 1);

    float o[8][4];
#pragma unroll
    for (int i = 0; i < 8; i++)
#pragma unroll
        for (int q = 0; q < 4; q++) o[i][q] = 0.0f;
    float mrow[2] = {-1e30f, -1e30f};
    float lrow[2] = {0.0f, 0.0f};

    uint32_t aQh[4][4], aQl[4][4];
    const int qr = lane >> 2, qc = lane & 3;

    for (int kt = 0; kt <= qt; kt++) {
        int s = kt & 1;
        if (kt + 1 <= qt) { CP_WAIT(1); } else { CP_WAIT(0); }
        __syncthreads();

        if (kt == 0) {
#pragma unroll
            for (int ks = 0; ks < 4; ks++) {
                ldsm4(aQh[ks], fa_a(sQh, w * 16, ks, lane));
                ldsm4(aQl[ks], fa_a(sQl, w * 16, ks, lane));
            }
        }

        uint32_t tKh = sKV + s * ATT_KV_STAGE;
        uint32_t tKl = tKh + ATT_TILE_B;
        uint32_t tVh = tKh + 2 * ATT_TILE_B;
        uint32_t tVl = tKh + 3 * ATT_TILE_B;

        // ---- S = Q @ K^T ----
        float sfr[16][4];
#pragma unroll
        for (int i = 0; i < 16; i++)
#pragma unroll
            for (int q = 0; q < 4; q++) sfr[i][q] = 0.0f;

#pragma unroll
        for (int ks = 0; ks < 4; ks++)
#pragma unroll
            for (int np = 0; np < 4; np++) {
                int ng0 = 2 * np, ng1 = 2 * np + 1;
                uint32_t bhA[4], blA[4], bhB[4], blB[4];
                ldsm4(bhA, fa_b(tKh, ng0 * 16, ks, lane));
                ldsm4(blA, fa_b(tKl, ng0 * 16, ks, lane));
                ldsm4(bhB, fa_b(tKh, ng1 * 16, ks, lane));
                ldsm4(blB, fa_b(tKl, ng1 * 16, ks, lane));
                mma16816(sfr[2 * ng0],     aQh[ks], &bhA[0]);
                mma16816(sfr[2 * ng0 + 1], aQh[ks], &bhA[2]);
                mma16816(sfr[2 * ng1],     aQh[ks], &bhB[0]);
                mma16816(sfr[2 * ng1 + 1], aQh[ks], &bhB[2]);
                mma16816(sfr[2 * ng0],     aQh[ks], &blA[0]);
                mma16816(sfr[2 * ng0 + 1], aQh[ks], &blA[2]);
                mma16816(sfr[2 * ng1],     aQh[ks], &blB[0]);
                mma16816(sfr[2 * ng1 + 1], aQh[ks], &blB[2]);
                mma16816(sfr[2 * ng0],     aQl[ks], &bhA[0]);
                mma16816(sfr[2 * ng0 + 1], aQl[ks], &bhA[2]);
                mma16816(sfr[2 * ng1],     aQl[ks], &bhB[0]);
                mma16816(sfr[2 * ng1 + 1], aQl[ks], &bhB[2]);
            }

        // ---- causal mask (diagonal tile only) ----
        if (kt == qt) {
            int r0 = w * 16 + qr;
#pragma unroll
            for (int nf = 0; nf < 16; nf++) {
                int c0 = nf * 8 + qc * 2;
                if (c0 > r0)     sfr[nf][0] = -1e30f;
                if (c0 + 1 > r0) sfr[nf][1] = -1e30f;
                if (c0 > r0 + 8)     sfr[nf][2] = -1e30f;
                if (c0 + 1 > r0 + 8) sfr[nf][3] = -1e30f;
            }
        }

        // ---- global row max (must complete before any exp) ----
        float tm0 = -1e30f, tm1 = -1e30f;
#pragma unroll
        for (int nf = 0; nf < 16; nf++) {
            tm0 = fmaxf(tm0, fmaxf(sfr[nf][0], sfr[nf][1]));
            tm1 = fmaxf(tm1, fmaxf(sfr[nf][2], sfr[nf][3]));
        }
#pragma unroll
        for (int off = 1; off <= 2; off <<= 1) {
            tm0 = fmaxf(tm0, __shfl_xor_sync(0xffffffffu, tm0, off));
            tm1 = fmaxf(tm1, __shfl_xor_sync(0xffffffffu, tm1, off));
        }
        float mn0 = fmaxf(mrow[0], tm0), mn1 = fmaxf(mrow[1], tm1);
        float al0 = exp2f(mrow[0] - mn0), al1 = exp2f(mrow[1] - mn1);
        mrow[0] = mn0; mrow[1] = mn1;
#pragma unroll
        for (int i = 0; i < 8; i++) {
            o[i][0] *= al0; o[i][1] *= al0;
            o[i][2] *= al1; o[i][3] *= al1;
        }

        // ---- fused per-group pipeline: exp -> rs -> pack -> PV MMAs ----
        // MUFU (exp) and FMA (pack/residual) work of group ks overlaps the
        // tensor work of neighboring groups in ptxas's scheduling window.
        float rs0 = 0.0f, rs1 = 0.0f;
#pragma unroll
        for (int ks = 0; ks < 8; ks++) {
            float* f0 = sfr[2 * ks];
            float* f1 = sfr[2 * ks + 1];
            f0[0] = exp2f(f0[0] - mn0);
            f0[1] = exp2f(f0[1] - mn0);
            f0[2] = exp2f(f0[2] - mn1);
            f0[3] = exp2f(f0[3] - mn1);
            f1[0] = exp2f(f1[0] - mn0);
            f1[1] = exp2f(f1[1] - mn0);
            f1[2] = exp2f(f1[2] - mn1);
            f1[3] = exp2f(f1[3] - mn1);
            rs0 += f0[0] + f0[1] + f1[0] + f1[1];
            rs1 += f0[2] + f0[3] + f1[2] + f1[3];

            uint32_t phx[4], plx[4];
            phx[0] = pack_bf2(f0[0], f0[1]);
            phx[1] = pack_bf2(f0[2], f0[3]);
            phx[2] = pack_bf2(f1[0], f1[1]);
            phx[3] = pack_bf2(f1[2], f1[3]);
            {
                __nv_bfloat162 h0 = *(__nv_bfloat162*)&phx[0];
                __nv_bfloat162 h1 = *(__nv_bfloat162*)&phx[1];
                __nv_bfloat162 h2 = *(__nv_bfloat162*)&phx[2];
                __nv_bfloat162 h3 = *(__nv_bfloat162*)&phx[3];
                plx[0] = pack_bf2(f0[0] - __bfloat162float(h0.x), f0[1] - __bfloat162float(h0.y));
                plx[1] = pack_bf2(f0[2] - __bfloat162float(h1.x), f0[3] - __bfloat162float(h1.y));
                plx[2] = pack_bf2(f1[0] - __bfloat162float(h2.x), f1[1] - __bfloat162float(h2.y));
                plx[3] = pack_bf2(f1[2] - __bfloat162float(h3.x), f1[3] - __bfloat162float(h3.y));
            }
#pragma unroll
            for (int gp = 0; gp < 2; gp++) {
                int ng0 = 2 * gp, ng1 = 2 * gp + 1;
                uint32_t vhA[4], vlA[4], vhB[4], vlB[4];
                ldsm4t(vhA, fa_v(tVh, ks * 16, ng0 * 16, lane));
                ldsm4t(vlA, fa_v(tVl, ks * 16, ng0 * 16, lane));
                ldsm4t(vhB, fa_v(tVh, ks * 16, ng1 * 16, lane));
                ldsm4t(vlB, fa_v(tVl, ks * 16, ng1 * 16, lane));
                mma16816(o[2 * ng0],     phx, &vhA[0]);
                mma16816(o[2 * ng0 + 1], phx, &vhA[2]);
                mma16816(o[2 * ng1],     phx, &vhB[0]);
                mma16816(o[2 * ng1 + 1], phx, &vhB[2]);
                mma16816(o[2 * ng0],     plx, &vhA[0]);
                mma16816(o[2 * ng0 + 1], plx, &vhA[2]);
                mma16816(o[2 * ng1],     plx, &vhB[0]);
                mma16816(o[2 * ng1 + 1], plx, &vhB[2]);
                mma16816(o[2 * ng0],     phx, &vlA[0]);
                mma16816(o[2 * ng0 + 1], phx, &vlA[2]);
                mma16816(o[2 * ng1],     phx, &vlB[0]);
                mma16816(o[2 * ng1 + 1], phx, &vlB[2]);
            }
        }

        // ---- deferred reductions (off the tensor critical path) ----
#pragma unroll
        for (int off = 1; off <= 2; off <<= 1) {
            rs0 += __shfl_xor_sync(0xffffffffu, rs0, off);
            rs1 += __shfl_xor_sync(0xffffffffu, rs1, off);
        }
        lrow[0] = lrow[0] * al0 + rs0;
        lrow[1] = lrow[1] * al1 + rs1;

        __syncthreads();
        if (kt + 2 <= qt) fillkv(kt + 2, s);
    }

    float inv0 = 1.0f / lrow[0];
    float inv1 = 1.0f / lrow[1];
    size_t r0 = rowbase + w * 16 + qr;
#pragma unroll
    for (int i = 0; i < 8; i++) {
        int col = hoff + i * 8 + qc * 2;
        float x0 = o[i][0] * inv0, x1 = o[i][1] * inv0;
        float x2 = o[i][2] * inv1, x3 = o[i][3] * inv1;
        __nv_bfloat16 h0 = __float2bfloat16(x0), h1 = __float2bfloat16(x1);
        __nv_bfloat16 h2 = __float2bfloat16(x2), h3 = __float2bfloat16(x3);
        size_t i0 = r0 * DD + col;
        size_t i1 = (r0 + 8) * DD + col;
        *(__nv_bfloat162*)(yh + i0) = __halves2bfloat162(h0, h1);
        *(__nv_bfloat162*)(yh + i1) = __halves2bfloat162(h2, h3);
        *(__nv_bfloat162*)(yl + i0) = __floats2bfloat162_rn(
            x0 - __bfloat162float(h0), x1 - __bfloat162float(h1));
        *(__nv_bfloat162*)(yl + i1) = __floats2bfloat162_rn(
            x2 - __bfloat162float(h2), x3 - __bfloat162float(h3));
    }
}

// ---------------------------------------------------------------------------
extern "C" void kernel_launch(void* const* d_in, const int* in_sizes, int n_in,
                              void* d_out, int out_size)
{
    const float* x      = (const float*)d_in[0];
    const float* W_attn = (const float*)d_in[1];
    const float* b_attn = (const float*)d_in[2];
    const float* W_proj = (const float*)d_in[3];
    const float* b_proj = (const float*)d_in[4];
    float* out = (float*)d_out;

    __nv_bfloat16 *xh, *xl, *qhp, *qlp, *khp, *klp, *vhp, *vlp, *yhp, *ylp;
    __nv_bfloat16 *wah, *wal, *wph, *wpl;
    cudaGetSymbolAddress((void**)&xh,  g_xh);
    cudaGetSymbolAddress((void**)&xl,  g_xl);
    cudaGetSymbolAddress((void**)&qhp, g_qh);
    cudaGetSymbolAddress((void**)&qlp, g_ql);
    cudaGetSymbolAddress((void**)&khp, g_kh);
    cudaGetSymbolAddress((void**)&klp, g_kl);
    cudaGetSymbolAddress((void**)&vhp, g_vh);
    cudaGetSymbolAddress((void**)&vlp, g_vl);
    cudaGetSymbolAddress((void**)&yhp, g_yh);
    cudaGetSymbolAddress((void**)&ylp, g_yl);
    cudaGetSymbolAddress((void**)&wah, g_wah);
    cudaGetSymbolAddress((void**)&wal, g_wal);
    cudaGetSymbolAddress((void**)&wph, g_wph);
    cudaGetSymbolAddress((void**)&wpl, g_wpl);

    cudaFuncSetAttribute(gemm_mma_bf16x3, cudaFuncAttributeMaxDynamicSharedMemorySize,
                         (int)GEMM_SMEM);
    cudaFuncSetAttribute(flash_attn_mma, cudaFuncAttributeMaxDynamicSharedMemorySize,
                         (int)ATT_SMEM);

    split_kernel<<<(MROWS * KDIM / 4 + 255) / 256, 256>>>(x, xh, xl, MROWS * KDIM / 4);
    wsplit_t2<<<dim3(128, KDIM / 32), dim3(32, 8)>>>(W_attn, wah, wal, W_proj, wph, wpl);

    gemm_mma_bf16x3<<<dim3(3 * DD / GBN, MROWS / GBM), 256, GEMM_SMEM>>>(
        xh, xl, wah, wal, b_attn, nullptr, 3 * DD, 1,
        qhp, qlp, khp, klp, vhp, vlp);

    flash_attn_mma<<<dim3(SS / 128, HH, BB), 256, ATT_SMEM>>>(
        qhp, qlp, khp, klp, vhp, vlp, yhp, ylp);

    gemm_mma_bf16x3<<<dim3(DD / GBN, MROWS / GBM), 256, GEMM_SMEM>>>(
        yhp, ylp, wph, wpl, b_proj, out, DD, 0,
        nullptr, nullptr, nullptr, nullptr, nullptr, nullptr);
}

// round 12
// speedup vs baseline: 1.0401x; 1.0160x over previous
#include <cuda_runtime.h>
#include <cuda_bf16.h>
#include <math.h>
#include <stdint.h>

// Problem shape (fixed by the reference)
#define BB 4
#define SS 2048
#define DD 1024
#define HH 16
#define HDIM 64
#define MROWS (BB * SS)          // 8192
#define KDIM 1024

// ---------------------------------------------------------------------------
// Scratch: device globals (no cudaMalloc allowed)
// ---------------------------------------------------------------------------
__device__ __nv_bfloat16 g_xh[(size_t)MROWS * KDIM];
__device__ __nv_bfloat16 g_xl[(size_t)MROWS * KDIM];
__device__ __nv_bfloat16 g_qh[(size_t)MROWS * DD];
__device__ __nv_bfloat16 g_ql[(size_t)MROWS * DD];
__device__ __nv_bfloat16 g_kh[(size_t)MROWS * DD];
__device__ __nv_bfloat16 g_kl[(size_t)MROWS * DD];
__device__ __nv_bfloat16 g_vh[(size_t)MROWS * DD];
__device__ __nv_bfloat16 g_vl[(size_t)MROWS * DD];
__device__ __nv_bfloat16 g_yh[(size_t)MROWS * KDIM];
__device__ __nv_bfloat16 g_yl[(size_t)MROWS * KDIM];
__device__ __nv_bfloat16 g_wah[(size_t)3 * DD * KDIM];   // W_attn^T hi/lo [N,K]
__device__ __nv_bfloat16 g_wal[(size_t)3 * DD * KDIM];
__device__ __nv_bfloat16 g_wph[(size_t)DD * KDIM];       // W_proj^T hi/lo [N,K]
__device__ __nv_bfloat16 g_wpl[(size_t)DD * KDIM];

// ---------------------------------------------------------------------------
// PTX helpers (base ISA only: cp.async / ldmatrix / mma.sync)
// ---------------------------------------------------------------------------
__device__ __forceinline__ uint32_t smem_u32(const void* p) {
    uint32_t a;
    asm("{ .reg .u64 t; cvta.to.shared.u64 t, %1; cvt.u32.u64 %0, t; }"
        : "=r"(a) : "l"(p));
    return a;
}

#define CP16(smem, gptr) \
    asm volatile("cp.async.cg.shared.global [%0], [%1], 16;" :: "r"(smem), "l"(gptr))
#define CP_COMMIT() asm volatile("cp.async.commit_group;" ::: "memory")
#define CP_WAIT(n)  asm volatile("cp.async.wait_group %0;" :: "n"(n) : "memory")

__device__ __forceinline__ void ldsm4(uint32_t* r, uint32_t addr) {
    asm volatile("ldmatrix.sync.aligned.m8n8.x4.shared.b16 {%0,%1,%2,%3}, [%4];"
                 : "=r"(r[0]), "=r"(r[1]), "=r"(r[2]), "=r"(r[3]) : "r"(addr));
}
__device__ __forceinline__ void ldsm4t(uint32_t* r, uint32_t addr) {
    asm volatile("ldmatrix.sync.aligned.m8n8.x4.trans.shared.b16 {%0,%1,%2,%3}, [%4];"
                 : "=r"(r[0]), "=r"(r[1]), "=r"(r[2]), "=r"(r[3]) : "r"(addr));
}

__device__ __forceinline__ void mma16816(float* c, const uint32_t* a, const uint32_t* b) {
    asm volatile(
        "mma.sync.aligned.m16n8k16.row.col.f32.bf16.bf16.f32 "
        "{%0,%1,%2,%3}, {%4,%5,%6,%7}, {%8,%9}, {%0,%1,%2,%3};"
        : "+f"(c[0]), "+f"(c[1]), "+f"(c[2]), "+f"(c[3])
        : "r"(a[0]), "r"(a[1]), "r"(a[2]), "r"(a[3]), "r"(b[0]), "r"(b[1]));
}

__device__ __forceinline__ uint32_t pack_bf2(float a, float b) {
    __nv_bfloat162 t = __floats2bfloat162_rn(a, b);
    return *(uint32_t*)&t;
}

// ---------------------------------------------------------------------------
// Split fp32 -> bf16 hi + bf16 lo
// ---------------------------------------------------------------------------
__global__ __launch_bounds__(256) void split_kernel(
    const float* __restrict__ in, __nv_bfloat16* __restrict__ hi,
    __nv_bfloat16* __restrict__ lo, int n4)
{
    int i = blockIdx.x * 256 + threadIdx.x;
    if (i >= n4) return;
    float4 v = ((const float4*)in)[i];
    __nv_bfloat16 h0 = __float2bfloat16(v.x), h1 = __float2bfloat16(v.y);
    __nv_bfloat16 h2 = __float2bfloat16(v.z), h3 = __float2bfloat16(v.w);
    __nv_bfloat162* hp = (__nv_bfloat162*)hi;
    __nv_bfloat162* lp = (__nv_bfloat162*)lo;
    hp[2 * i + 0] = __halves2bfloat162(h0, h1);
    hp[2 * i + 1] = __halves2bfloat162(h2, h3);
    lp[2 * i + 0] = __floats2bfloat162_rn(v.x - __bfloat162float(h0),
                                          v.y - __bfloat162float(h1));
    lp[2 * i + 1] = __floats2bfloat162_rn(v.z - __bfloat162float(h2),
                                          v.w - __bfloat162float(h3));
}

// ---------------------------------------------------------------------------
// Transpose + split BOTH weight matrices in one launch.
// ---------------------------------------------------------------------------
__global__ void wsplit_t2(const float* __restrict__ Wa, __nv_bfloat16* __restrict__ bah,
                          __nv_bfloat16* __restrict__ bal,
                          const float* __restrict__ Wp, __nv_bfloat16* __restrict__ bph,
                          __nv_bfloat16* __restrict__ bpl)
{
    __shared__ float t[32][33];
    int bx = blockIdx.x;
    const float* W;
    __nv_bfloat16 *bh, *bl;
    int Nd, n0;
    if (bx < 96) { W = Wa; bh = bah; bl = bal; Nd = 3 * DD; n0 = bx * 32; }
    else         { W = Wp; bh = bph; bl = bpl; Nd = DD;     n0 = (bx - 96) * 32; }
    int k0 = blockIdx.y * 32;
    int tx = threadIdx.x, ty = threadIdx.y;   // block (32, 8)
    for (int r = ty; r < 32; r += 8)
        t[r][tx] = W[(size_t)(k0 + r) * Nd + n0 + tx];
    __syncthreads();
    for (int r = ty; r < 32; r += 8) {
        float v = t[tx][r];
        __nv_bfloat16 h = __float2bfloat16(v);
        bh[(size_t)(n0 + r) * KDIM + k0 + tx] = h;
        bl[(size_t)(n0 + r) * KDIM + k0 + tx] = __float2bfloat16(v - __bfloat162float(h));
    }
}

// ---------------------------------------------------------------------------
// mma.sync bf16x3 GEMM, 2 CTAs/SM (unchanged — best measured)
// ---------------------------------------------------------------------------
#define GBM 128
#define GBN 128
#define GBK 32
#define TILE_BYTES (64 * 128)
#define STAGE_BYTES (4 * TILE_BYTES)
#define NSTAGE 3
#define GEMM_SMEM (NSTAGE * STAGE_BYTES)     // 98304

// q scale: hd^-0.5 * log2(e), so softmax can run in exp2 domain
#define QSCALE (0.125f * 1.4426950408889634f)

__device__ __forceinline__ uint32_t a_addr(uint32_t tb, int m0, int ks, int lane) {
    int row = m0 + (lane & 15);
    int p = row >> 1;
    int chl = ((row & 1) << 2) | (ks << 1) | (lane >> 4);
    return tb + p * 128 + ((chl ^ (p & 7)) << 4);
}
__device__ __forceinline__ uint32_t b_addr(uint32_t tb, int n0, int ks, int lane) {
    int row = n0 + (lane & 7) + ((lane >> 4) << 3);
    int p = row >> 1;
    int chl = ((row & 1) << 2) | (ks << 1) | ((lane >> 3) & 1);
    return tb + p * 128 + ((chl ^ (p & 7)) << 4);
}

__global__ __launch_bounds__(256, 2) void gemm_mma_bf16x3(
    const __nv_bfloat16* __restrict__ Ah, const __nv_bfloat16* __restrict__ Al,
    const __nv_bfloat16* __restrict__ Bh, const __nv_bfloat16* __restrict__ Bl,
    const float* __restrict__ bias, float* __restrict__ C, int Nld, int mode,
    __nv_bfloat16* __restrict__ oqh, __nv_bfloat16* __restrict__ oql,
    __nv_bfloat16* __restrict__ okh, __nv_bfloat16* __restrict__ okl,
    __nv_bfloat16* __restrict__ ovh, __nv_bfloat16* __restrict__ ovl)
{
    extern __shared__ __align__(1024) char smraw[];
    const uint32_t sbase = smem_u32(smraw);
    const int tid = threadIdx.x;
    const int lane = tid & 31;
    const int wid = tid >> 5;
    const int wm = wid & 1;
    const int wn = wid >> 1;
    const int row0 = blockIdx.y * GBM;
    const int col0 = blockIdx.x * GBN;

    const int frow = tid >> 2;
    const int fkc  = tid & 3;
    uint32_t so0, so1;
    {
        int p0 = frow >> 1;
        int c0 = (((frow & 1) << 2) | fkc) ^ (p0 & 7);
        so0 = (uint32_t)(p0 * 128 + c0 * 16);
        int r1 = frow + 64;
        int p1 = r1 >> 1;
        int c1 = (((r1 & 1) << 2) | fkc) ^ (p1 & 7);
        so1 = (uint32_t)(p1 * 128 + c1 * 16);
    }
    const __nv_bfloat16* fs0 = Ah + (size_t)(row0 + frow) * KDIM + fkc * 8;
    const __nv_bfloat16* fs1 = Al + (size_t)(row0 + frow) * KDIM + fkc * 8;
    const __nv_bfloat16* fs2 = Bh + (size_t)(col0 + frow) * KDIM + fkc * 8;
    const __nv_bfloat16* fs3 = Bl + (size_t)(col0 + frow) * KDIM + fkc * 8;
    const size_t rstep = (size_t)64 * KDIM;

    float acc[4][4][4];
#pragma unroll
    for (int mi = 0; mi < 4; mi++)
#pragma unroll
        for (int ni = 0; ni < 4; ni++)
#pragma unroll
            for (int q = 0; q < 4; q++) acc[mi][ni][q] = 0.0f;

    auto fill = [&](int s) {
        uint32_t stg = sbase + s * STAGE_BYTES;
        CP16(stg + so0, fs0);                  CP16(stg + so1, fs0 + rstep);
        CP16(stg + TILE_BYTES + so0, fs1);     CP16(stg + TILE_BYTES + so1, fs1 + rstep);
        CP16(stg + 2 * TILE_BYTES + so0, fs2); CP16(stg + 2 * TILE_BYTES + so1, fs2 + rstep);
        CP16(stg + 3 * TILE_BYTES + so0, fs3); CP16(stg + 3 * TILE_BYTES + so1, fs3 + rstep);
        fs0 += GBK; fs1 += GBK; fs2 += GBK; fs3 += GBK;
        CP_COMMIT();
    };

    fill(0);
    fill(1);

    const int NCH = KDIM / GBK;   // 32
    for (int c = 0; c < NCH; c++) {
        int s = c % 3;
        if (c + 2 < NCH) { CP_WAIT(1); } else { CP_WAIT(0); }
        __syncthreads();
        if (c + 2 < NCH) fill((c + 2) % 3);

        uint32_t st = sbase + s * STAGE_BYTES;
#pragma unroll
        for (int ks = 0; ks < 2; ks++) {
            uint32_t aH[4][4], aL[4][4];
#pragma unroll
            for (int mi = 0; mi < 4; mi++) {
                ldsm4(aH[mi], a_addr(st,              wm * 64 + mi * 16, ks, lane));
                ldsm4(aL[mi], a_addr(st + TILE_BYTES, wm * 64 + mi * 16, ks, lane));
            }
#pragma unroll
            for (int g = 0; g < 2; g++) {
                uint32_t bh[4], bl[4];
                ldsm4(bh, b_addr(st + 2 * TILE_BYTES, wn * 32 + g * 16, ks, lane));
                ldsm4(bl, b_addr(st + 3 * TILE_BYTES, wn * 32 + g * 16, ks, lane));
#pragma unroll
                for (int mi = 0; mi < 4; mi++) {
                    mma16816(acc[mi][2 * g],     aH[mi], &bh[0]);
                    mma16816(acc[mi][2 * g + 1], aH[mi], &bh[2]);
                }
#pragma unroll
                for (int mi = 0; mi < 4; mi++) {
                    mma16816(acc[mi][2 * g],     aH[mi], &bl[0]);
                    mma16816(acc[mi][2 * g + 1], aH[mi], &bl[2]);
                }
#pragma unroll
                for (int mi = 0; mi < 4; mi++) {
                    mma16816(acc[mi][2 * g],     aL[mi], &bh[0]);
                    mma16816(acc[mi][2 * g + 1], aL[mi], &bh[2]);
                }
            }
        }
    }

    const int qr = lane >> 2, qc = lane & 3;
    if (mode == 0) {
#pragma unroll
        for (int mi = 0; mi < 4; mi++)
#pragma unroll
            for (int ni = 0; ni < 4; ni++) {
                int row = row0 + wm * 64 + mi * 16 + qr;
                int col = col0 + wn * 32 + ni * 8 + qc * 2;
                float2 bv = *(const float2*)(bias + col);
                float2 v0, v1;
                v0.x = acc[mi][ni][0] + bv.x;  v0.y = acc[mi][ni][1] + bv.y;
                v1.x = acc[mi][ni][2] + bv.x;  v1.y = acc[mi][ni][3] + bv.y;
                *(float2*)(C + (size_t)row * Nld + col) = v0;
                *(float2*)(C + (size_t)(row + 8) * Nld + col) = v1;
            }
    } else {
        int t = col0 >> 10;
        __nv_bfloat16* oh = (t == 0) ? oqh : (t == 1) ? okh : ovh;
        __nv_bfloat16* ol = (t == 0) ? oql : (t == 1) ? okl : ovl;
        float sc = (t == 0) ? QSCALE : 1.0f;   // q in exp2 domain
#pragma unroll
        for (int mi = 0; mi < 4; mi++)
#pragma unroll
            for (int ni = 0; ni < 4; ni++) {
                int row = row0 + wm * 64 + mi * 16 + qr;
                int gcol = col0 + wn * 32 + ni * 8 + qc * 2;
                int lcol = gcol & 1023;
                float2 bv = *(const float2*)(bias + gcol);
                float x0 = (acc[mi][ni][0] + bv.x) * sc;
                float x1 = (acc[mi][ni][1] + bv.y) * sc;
                float x2 = (acc[mi][ni][2] + bv.x) * sc;
                float x3 = (acc[mi][ni][3] + bv.y) * sc;
                __nv_bfloat16 h0 = __float2bfloat16(x0), h1 = __float2bfloat16(x1);
                __nv_bfloat16 h2 = __float2bfloat16(x2), h3 = __float2bfloat16(x3);
                size_t i0 = (size_t)row * DD + lcol;
                size_t i1 = (size_t)(row + 8) * DD + lcol;
                *(__nv_bfloat162*)(oh + i0) = __halves2bfloat162(h0, h1);
                *(__nv_bfloat162*)(oh + i1) = __halves2bfloat162(h2, h3);
                *(__nv_bfloat162*)(ol + i0) = __floats2bfloat162_rn(
                    x0 - __bfloat162float(h0), x1 - __bfloat162float(h1));
                *(__nv_bfloat162*)(ol + i1) = __floats2bfloat162_rn(
                    x2 - __bfloat162float(h2), x3 - __bfloat162float(h3));
            }
    }
}

// ---------------------------------------------------------------------------
// Flash attention, mma.sync bf16x3, causal.
// NEW: 128-thread CTAs (4 warps), 64-row Q tile, 128-row KV tile single-
// buffered. Per-warp structure identical to the best (R9) kernel, but the
// register cap at 2 CTAs/SM is 256 (not 128) so regs=244 fits WITHOUT spills.
// Two independent CTAs per SM: one CTA's PV MMAs overlap the other's
// softmax/shuffle phases (the mechanism that raised GEMM 57%->69%).
// SMEM: Q hi/lo 2x8KB + KV 4x16KB = 80KB -> 2 CTAs = 160KB <= 228KB.
// ---------------------------------------------------------------------------
#define ATT_Q_B 8192                           // 64 rows x 128 B
#define ATT_KV_T 16384                         // 128 rows x 128 B per tensor
#define ATT_SMEM (2 * ATT_Q_B + 4 * ATT_KV_T)  // 81920

__device__ __forceinline__ uint32_t sw128(uint32_t tb, int row, int chunk) {
    return tb + row * 128 + ((chunk ^ (row & 7)) << 4);
}
__device__ __forceinline__ uint32_t fa_a(uint32_t tb, int m0, int ks, int lane) {
    int row = m0 + (lane & 15);
    return sw128(tb, row, ks * 2 + (lane >> 4));
}
__device__ __forceinline__ uint32_t fa_b(uint32_t tb, int n0, int ks, int lane) {
    int row = n0 + (lane & 7) + ((lane >> 4) << 3);
    return sw128(tb, row, ks * 2 + ((lane >> 3) & 1));
}
__device__ __forceinline__ uint32_t fa_v(uint32_t tb, int kv0, int hd0, int lane) {
    int row = kv0 + (((lane >> 3) & 1) << 3) + (lane & 7);
    return sw128(tb, row, (hd0 >> 3) + (lane >> 4));
}

__global__ __launch_bounds__(128, 2) void flash_attn_mma(
    const __nv_bfloat16* __restrict__ qh, const __nv_bfloat16* __restrict__ ql,
    const __nv_bfloat16* __restrict__ kh, const __nv_bfloat16* __restrict__ kl,
    const __nv_bfloat16* __restrict__ vh, const __nv_bfloat16* __restrict__ vl,
    __nv_bfloat16* __restrict__ yh, __nv_bfloat16* __restrict__ yl)
{
    extern __shared__ __align__(1024) char smraw[];
    const uint32_t sb = smem_u32(smraw);
    const int qt = blockIdx.x, h = blockIdx.y, b = blockIdx.z;
    const int tid = threadIdx.x, lane = tid & 31, w = tid >> 5;   // w in 0..3
    const size_t rowbase = (size_t)(b * SS) + qt * 64;
    const int hoff = h * HDIM;

    const uint32_t sQh = sb, sQl = sb + ATT_Q_B;
    const uint32_t tKh = sb + 2 * ATT_Q_B;
    const uint32_t tKl = tKh + ATT_KV_T;
    const uint32_t tVh = tKh + 2 * ATT_KV_T;
    const uint32_t tVl = tKh + 3 * ATT_KV_T;

    // one-time Q load (64 rows x 64 cols, hi+lo) — completes with first CP_WAIT
    {
        const __nv_bfloat16* qs[2] = {qh, ql};
        for (int i = tid; i < 1024; i += 128) {
            int t = i >> 9, idx = i & 511, r = idx >> 3, ch = idx & 7;
            CP16(sw128(t ? sQl : sQh, r, ch),
                 qs[t] + (rowbase + r) * DD + hoff + ch * 8);
        }
        CP_COMMIT();
    }

    const __nv_bfloat16* kvs[4] = {kh, kl, vh, vl};
    auto fillkv = [&](int kt) {
        size_t kvrow = (size_t)(b * SS) + (size_t)kt * 128;
        for (int i = tid; i < 4096; i += 128) {
            int t = i >> 10, idx = i & 1023, r = idx >> 3, ch = idx & 7;
            CP16(sw128(tKh + t * ATT_KV_T, r, ch),
                 kvs[t] + (kvrow + r) * DD + hoff + ch * 8);
        }
        CP_COMMIT();
    };

    float o[8][4];
#pragma unroll
    for (int i = 0; i < 8; i++)
#pragma unroll
        for (int q = 0; q < 4; q++) o[i][q] = 0.0f;
    float mrow[2] = {-1e30f, -1e30f};
    float lrow[2] = {0.0f, 0.0f};

    uint32_t aQh[4][4], aQl[4][4];
    const int qr = lane >> 2, qc = lane & 3;

    const int nkt = (qt + 2) >> 1;   // ceil((qt+1)*64 / 128)

    for (int kt = 0; kt < nkt; kt++) {
        fillkv(kt);
        CP_WAIT(0);
        __syncthreads();

        if (kt == 0) {
#pragma unroll
            for (int ks = 0; ks < 4; ks++) {
                ldsm4(aQh[ks], fa_a(sQh, w * 16, ks, lane));
                ldsm4(aQl[ks], fa_a(sQl, w * 16, ks, lane));
            }
        }

        // ---- S = Q @ K^T ----
        float sfr[16][4];
#pragma unroll
        for (int i = 0; i < 16; i++)
#pragma unroll
            for (int q = 0; q < 4; q++) sfr[i][q] = 0.0f;

#pragma unroll
        for (int ks = 0; ks < 4; ks++)
#pragma unroll
            for (int np = 0; np < 4; np++) {
                int ng0 = 2 * np, ng1 = 2 * np + 1;
                uint32_t bhA[4], blA[4], bhB[4], blB[4];
                ldsm4(bhA, fa_b(tKh, ng0 * 16, ks, lane));
                ldsm4(blA, fa_b(tKl, ng0 * 16, ks, lane));
                ldsm4(bhB, fa_b(tKh, ng1 * 16, ks, lane));
                ldsm4(blB, fa_b(tKl, ng1 * 16, ks, lane));
                mma16816(sfr[2 * ng0],     aQh[ks], &bhA[0]);
                mma16816(sfr[2 * ng0 + 1], aQh[ks], &bhA[2]);
                mma16816(sfr[2 * ng1],     aQh[ks], &bhB[0]);
                mma16816(sfr[2 * ng1 + 1], aQh[ks], &bhB[2]);
                mma16816(sfr[2 * ng0],     aQh[ks], &blA[0]);
                mma16816(sfr[2 * ng0 + 1], aQh[ks], &blA[2]);
                mma16816(sfr[2 * ng1],     aQh[ks], &blB[0]);
                mma16816(sfr[2 * ng1 + 1], aQh[ks], &blB[2]);
                mma16816(sfr[2 * ng0],     aQl[ks], &bhA[0]);
                mma16816(sfr[2 * ng0 + 1], aQl[ks], &bhA[2]);
                mma16816(sfr[2 * ng1],     aQl[ks], &bhB[0]);
                mma16816(sfr[2 * ng1 + 1], aQl[ks], &bhB[2]);
            }

        // ---- causal mask (only the last KV tile overlaps the diagonal) ----
        if (kt == nkt - 1) {
            int r0 = w * 16 + qr;               // q row within tile (0..63)
            int cbase = kt * 128 - qt * 64;     // KV col offset rel. to q rows
#pragma unroll
            for (int nf = 0; nf < 16; nf++) {
                int c0 = cbase + nf * 8 + qc * 2;
                if (c0 > r0)     sfr[nf][0] = -1e30f;
                if (c0 + 1 > r0) sfr[nf][1] = -1e30f;
                if (c0 > r0 + 8)     sfr[nf][2] = -1e30f;
                if (c0 + 1 > r0 + 8) sfr[nf][3] = -1e30f;
            }
        }

        // ---- online softmax ----
        float tm0 = -1e30f, tm1 = -1e30f;
#pragma unroll
        for (int nf = 0; nf < 16; nf++) {
            tm0 = fmaxf(tm0, fmaxf(sfr[nf][0], sfr[nf][1]));
            tm1 = fmaxf(tm1, fmaxf(sfr[nf][2], sfr[nf][3]));
        }
#pragma unroll
        for (int off = 1; off <= 2; off <<= 1) {
            tm0 = fmaxf(tm0, __shfl_xor_sync(0xffffffffu, tm0, off));
            tm1 = fmaxf(tm1, __shfl_xor_sync(0xffffffffu, tm1, off));
        }
        float mn0 = fmaxf(mrow[0], tm0), mn1 = fmaxf(mrow[1], tm1);
        float al0 = exp2f(mrow[0] - mn0), al1 = exp2f(mrow[1] - mn1);
        mrow[0] = mn0; mrow[1] = mn1;
#pragma unroll
        for (int i = 0; i < 8; i++) {
            o[i][0] *= al0; o[i][1] *= al0;
            o[i][2] *= al1; o[i][3] *= al1;
        }

        float rs0 = 0.0f, rs1 = 0.0f;
#pragma unroll
        for (int nf = 0; nf < 16; nf++) {
            sfr[nf][0] = exp2f(sfr[nf][0] - mn0);
            sfr[nf][1] = exp2f(sfr[nf][1] - mn0);
            sfr[nf][2] = exp2f(sfr[nf][2] - mn1);
            sfr[nf][3] = exp2f(sfr[nf][3] - mn1);
            rs0 += sfr[nf][0] + sfr[nf][1];
            rs1 += sfr[nf][2] + sfr[nf][3];
        }

        // ---- O += P @ V ----
#pragma unroll
        for (int ks = 0; ks < 8; ks++) {
            const float* f0 = sfr[2 * ks];
            const float* f1 = sfr[2 * ks + 1];
            uint32_t phx[4], plx[4];
            phx[0] = pack_bf2(f0[0], f0[1]);
            phx[1] = pack_bf2(f0[2], f0[3]);
            phx[2] = pack_bf2(f1[0], f1[1]);
            phx[3] = pack_bf2(f1[2], f1[3]);
            {
                __nv_bfloat162 h0 = *(__nv_bfloat162*)&phx[0];
                __nv_bfloat162 h1 = *(__nv_bfloat162*)&phx[1];
                __nv_bfloat162 h2 = *(__nv_bfloat162*)&phx[2];
                __nv_bfloat162 h3 = *(__nv_bfloat162*)&phx[3];
                plx[0] = pack_bf2(f0[0] - __bfloat162float(h0.x), f0[1] - __bfloat162float(h0.y));
                plx[1] = pack_bf2(f0[2] - __bfloat162float(h1.x), f0[3] - __bfloat162float(h1.y));
                plx[2] = pack_bf2(f1[0] - __bfloat162float(h2.x), f1[1] - __bfloat162float(h2.y));
                plx[3] = pack_bf2(f1[2] - __bfloat162float(h3.x), f1[3] - __bfloat162float(h3.y));
            }
#pragma unroll
            for (int gp = 0; gp < 2; gp++) {
                int ng0 = 2 * gp, ng1 = 2 * gp + 1;
                uint32_t vhA[4], vlA[4], vhB[4], vlB[4];
                ldsm4t(vhA, fa_v(tVh, ks * 16, ng0 * 16, lane));
                ldsm4t(vlA, fa_v(tVl, ks * 16, ng0 * 16, lane));
                ldsm4t(vhB, fa_v(tVh, ks * 16, ng1 * 16, lane));
                ldsm4t(vlB, fa_v(tVl, ks * 16, ng1 * 16, lane));
                mma16816(o[2 * ng0],     phx, &vhA[0]);
                mma16816(o[2 * ng0 + 1], phx, &vhA[2]);
                mma16816(o[2 * ng1],     phx, &vhB[0]);
                mma16816(o[2 * ng1 + 1], phx, &vhB[2]);
                mma16816(o[2 * ng0],     plx, &vhA[0]);
                mma16816(o[2 * ng0 + 1], plx, &vhA[2]);
                mma16816(o[2 * ng1],     plx, &vhB[0]);
                mma16816(o[2 * ng1 + 1], plx, &vhB[2]);
                mma16816(o[2 * ng0],     phx, &vlA[0]);
                mma16816(o[2 * ng0 + 1], phx, &vlA[2]);
                mma16816(o[2 * ng1],     phx, &vlB[0]);
                mma16816(o[2 * ng1 + 1], phx, &vlB[2]);
            }
        }

        // deferred row-sum reduction (off the tensor critical path)
#pragma unroll
        for (int off = 1; off <= 2; off <<= 1) {
            rs0 += __shfl_xor_sync(0xffffffffu, rs0, off);
            rs1 += __shfl_xor_sync(0xffffffffu, rs1, off);
        }
        lrow[0] = lrow[0] * al0 + rs0;
        lrow[1] = lrow[1] * al1 + rs1;

        __syncthreads();   // all warps done reading KV before next overwrite
    }

    // ---- epilogue: O/l -> yh/yl ----
    float inv0 = 1.0f / lrow[0];
    float inv1 = 1.0f / lrow[1];
    size_t r0 = rowbase + w * 16 + qr;
#pragma unroll
    for (int i = 0; i < 8; i++) {
        int col = hoff + i * 8 + qc * 2;
        float x0 = o[i][0] * inv0, x1 = o[i][1] * inv0;
        float x2 = o[i][2] * inv1, x3 = o[i][3] * inv1;
        __nv_bfloat16 h0 = __float2bfloat16(x0), h1 = __float2bfloat16(x1);
        __nv_bfloat16 h2 = __float2bfloat16(x2), h3 = __float2bfloat16(x3);
        size_t i0 = r0 * DD + col;
        size_t i1 = (r0 + 8) * DD + col;
        *(__nv_bfloat162*)(yh + i0) = __halves2bfloat162(h0, h1);
        *(__nv_bfloat162*)(yh + i1) = __halves2bfloat162(h2, h3);
        *(__nv_bfloat162*)(yl + i0) = __floats2bfloat162_rn(
            x0 - __bfloat162float(h0), x1 - __bfloat162float(h1));
        *(__nv_bfloat162*)(yl + i1) = __floats2bfloat162_rn(
            x2 - __bfloat162float(h2), x3 - __bfloat162float(h3));
    }
}

// ---------------------------------------------------------------------------
extern "C" void kernel_launch(void* const* d_in, const int* in_sizes, int n_in,
                              void* d_out, int out_size)
{
    const float* x      = (const float*)d_in[0];
    const float* W_attn = (const float*)d_in[1];
    const float* b_attn = (const float*)d_in[2];
    const float* W_proj = (const float*)d_in[3];
    const float* b_proj = (const float*)d_in[4];
    float* out = (float*)d_out;

    __nv_bfloat16 *xh, *xl, *qhp, *qlp, *khp, *klp, *vhp, *vlp, *yhp, *ylp;
    __nv_bfloat16 *wah, *wal, *wph, *wpl;
    cudaGetSymbolAddress((void**)&xh,  g_xh);
    cudaGetSymbolAddress((void**)&xl,  g_xl);
    cudaGetSymbolAddress((void**)&qhp, g_qh);
    cudaGetSymbolAddress((void**)&qlp, g_ql);
    cudaGetSymbolAddress((void**)&khp, g_kh);
    cudaGetSymbolAddress((void**)&klp, g_kl);
    cudaGetSymbolAddress((void**)&vhp, g_vh);
    cudaGetSymbolAddress((void**)&vlp, g_vl);
    cudaGetSymbolAddress((void**)&yhp, g_yh);
    cudaGetSymbolAddress((void**)&ylp, g_yl);
    cudaGetSymbolAddress((void**)&wah, g_wah);
    cudaGetSymbolAddress((void**)&wal, g_wal);
    cudaGetSymbolAddress((void**)&wph, g_wph);
    cudaGetSymbolAddress((void**)&wpl, g_wpl);

    cudaFuncSetAttribute(gemm_mma_bf16x3, cudaFuncAttributeMaxDynamicSharedMemorySize,
                         (int)GEMM_SMEM);
    cudaFuncSetAttribute(flash_attn_mma, cudaFuncAttributeMaxDynamicSharedMemorySize,
                         (int)ATT_SMEM);

    split_kernel<<<(MROWS * KDIM / 4 + 255) / 256, 256>>>(x, xh, xl, MROWS * KDIM / 4);
    wsplit_t2<<<dim3(128, KDIM / 32), dim3(32, 8)>>>(W_attn, wah, wal, W_proj, wph, wpl);

    gemm_mma_bf16x3<<<dim3(3 * DD / GBN, MROWS / GBM), 256, GEMM_SMEM>>>(
        xh, xl, wah, wal, b_attn, nullptr, 3 * DD, 1,
        qhp, qlp, khp, klp, vhp, vlp);

    flash_attn_mma<<<dim3(SS / 64, HH, BB), 128, ATT_SMEM>>>(
        qhp, qlp, khp, klp, vhp, vlp, yhp, ylp);

    gemm_mma_bf16x3<<<dim3(DD / GBN, MROWS / GBM), 256, GEMM_SMEM>>>(
        yhp, ylp, wph, wpl, b_proj, out, DD, 0,
        nullptr, nullptr, nullptr, nullptr, nullptr, nullptr);
}

// round 13
// speedup vs baseline: 1.0455x; 1.0052x over previous
#include <cuda_runtime.h>
#include <cuda_bf16.h>
#include <math.h>
#include <stdint.h>

// Problem shape (fixed by the reference)
#define BB 4
#define SS 2048
#define DD 1024
#define HH 16
#define HDIM 64
#define MROWS (BB * SS)          // 8192
#define KDIM 1024

// ---------------------------------------------------------------------------
// Scratch: device globals (no cudaMalloc allowed)
// ---------------------------------------------------------------------------
__device__ __nv_bfloat16 g_xh[(size_t)MROWS * KDIM];
__device__ __nv_bfloat16 g_xl[(size_t)MROWS * KDIM];
__device__ __nv_bfloat16 g_qh[(size_t)MROWS * DD];
__device__ __nv_bfloat16 g_ql[(size_t)MROWS * DD];
__device__ __nv_bfloat16 g_kh[(size_t)MROWS * DD];
__device__ __nv_bfloat16 g_kl[(size_t)MROWS * DD];
__device__ __nv_bfloat16 g_vh[(size_t)MROWS * DD];
__device__ __nv_bfloat16 g_vl[(size_t)MROWS * DD];
__device__ __nv_bfloat16 g_yh[(size_t)MROWS * KDIM];
__device__ __nv_bfloat16 g_yl[(size_t)MROWS * KDIM];
__device__ __nv_bfloat16 g_wah[(size_t)3 * DD * KDIM];   // W_attn^T hi/lo [N,K]
__device__ __nv_bfloat16 g_wal[(size_t)3 * DD * KDIM];
__device__ __nv_bfloat16 g_wph[(size_t)DD * KDIM];       // W_proj^T hi/lo [N,K]
__device__ __nv_bfloat16 g_wpl[(size_t)DD * KDIM];

// ---------------------------------------------------------------------------
// PTX helpers (base ISA only: cp.async / ldmatrix / mma.sync)
// ---------------------------------------------------------------------------
__device__ __forceinline__ uint32_t smem_u32(const void* p) {
    uint32_t a;
    asm("{ .reg .u64 t; cvta.to.shared.u64 t, %1; cvt.u32.u64 %0, t; }"
        : "=r"(a) : "l"(p));
    return a;
}

#define CP16(smem, gptr) \
    asm volatile("cp.async.cg.shared.global [%0], [%1], 16;" :: "r"(smem), "l"(gptr))
#define CP_COMMIT() asm volatile("cp.async.commit_group;" ::: "memory")
#define CP_WAIT(n)  asm volatile("cp.async.wait_group %0;" :: "n"(n) : "memory")

__device__ __forceinline__ void ldsm4(uint32_t* r, uint32_t addr) {
    asm volatile("ldmatrix.sync.aligned.m8n8.x4.shared.b16 {%0,%1,%2,%3}, [%4];"
                 : "=r"(r[0]), "=r"(r[1]), "=r"(r[2]), "=r"(r[3]) : "r"(addr));
}
__device__ __forceinline__ void ldsm4t(uint32_t* r, uint32_t addr) {
    asm volatile("ldmatrix.sync.aligned.m8n8.x4.trans.shared.b16 {%0,%1,%2,%3}, [%4];"
                 : "=r"(r[0]), "=r"(r[1]), "=r"(r[2]), "=r"(r[3]) : "r"(addr));
}

__device__ __forceinline__ void mma16816(float* c, const uint32_t* a, const uint32_t* b) {
    asm volatile(
        "mma.sync.aligned.m16n8k16.row.col.f32.bf16.bf16.f32 "
        "{%0,%1,%2,%3}, {%4,%5,%6,%7}, {%8,%9}, {%0,%1,%2,%3};"
        : "+f"(c[0]), "+f"(c[1]), "+f"(c[2]), "+f"(c[3])
        : "r"(a[0]), "r"(a[1]), "r"(a[2]), "r"(a[3]), "r"(b[0]), "r"(b[1]));
}

__device__ __forceinline__ uint32_t pack_bf2(float a, float b) {
    __nv_bfloat162 t = __floats2bfloat162_rn(a, b);
    return *(uint32_t*)&t;
}

// ---------------------------------------------------------------------------
// Fused prep: one launch does x hi/lo split AND both weight transpose-splits.
// Blocks [0, XB): elementwise split of x (float4 chunks).
// Blocks [XB, XB+4096): transpose+split of W_attn / W_proj 32x32 tiles.
// ---------------------------------------------------------------------------
#define XB (MROWS * KDIM / 4 / 256)   // 8192 blocks for x

__global__ __launch_bounds__(256) void prep_fused(
    const float* __restrict__ x, __nv_bfloat16* __restrict__ xh,
    __nv_bfloat16* __restrict__ xl,
    const float* __restrict__ Wa, __nv_bfloat16* __restrict__ bah,
    __nv_bfloat16* __restrict__ bal,
    const float* __restrict__ Wp, __nv_bfloat16* __restrict__ bph,
    __nv_bfloat16* __restrict__ bpl)
{
    int bz = blockIdx.x;
    if (bz < XB) {
        int i = bz * 256 + threadIdx.x;
        float4 v = ((const float4*)x)[i];
        __nv_bfloat16 h0 = __float2bfloat16(v.x), h1 = __float2bfloat16(v.y);
        __nv_bfloat16 h2 = __float2bfloat16(v.z), h3 = __float2bfloat16(v.w);
        __nv_bfloat162* hp = (__nv_bfloat162*)xh;
        __nv_bfloat162* lp = (__nv_bfloat162*)xl;
        hp[2 * i + 0] = __halves2bfloat162(h0, h1);
        hp[2 * i + 1] = __halves2bfloat162(h2, h3);
        lp[2 * i + 0] = __floats2bfloat162_rn(v.x - __bfloat162float(h0),
                                              v.y - __bfloat162float(h1));
        lp[2 * i + 1] = __floats2bfloat162_rn(v.z - __bfloat162float(h2),
                                              v.w - __bfloat162float(h3));
        return;
    }
    // weight transpose+split
    __shared__ float t[32][33];
    int idx = bz - XB;               // 0..4095
    int bx = idx & 127;              // 128 col-tiles
    int by = idx >> 7;               // 32 k-tiles
    const float* W;
    __nv_bfloat16 *bh, *bl;
    int Nd, n0;
    if (bx < 96) { W = Wa; bh = bah; bl = bal; Nd = 3 * DD; n0 = bx * 32; }
    else         { W = Wp; bh = bph; bl = bpl; Nd = DD;     n0 = (bx - 96) * 32; }
    int k0 = by * 32;
    int tx = threadIdx.x & 31, ty = threadIdx.x >> 5;   // 32 x 8
    for (int r = ty; r < 32; r += 8)
        t[r][tx] = W[(size_t)(k0 + r) * Nd + n0 + tx];
    __syncthreads();
    for (int r = ty; r < 32; r += 8) {
        float v = t[tx][r];
        __nv_bfloat16 h = __float2bfloat16(v);
        bh[(size_t)(n0 + r) * KDIM + k0 + tx] = h;
        bl[(size_t)(n0 + r) * KDIM + k0 + tx] = __float2bfloat16(v - __bfloat162float(h));
    }
}

// ---------------------------------------------------------------------------
// mma.sync bf16x3 GEMM, 2 CTAs/SM (unchanged — best measured)
// ---------------------------------------------------------------------------
#define GBM 128
#define GBN 128
#define GBK 32
#define TILE_BYTES (64 * 128)
#define STAGE_BYTES (4 * TILE_BYTES)
#define NSTAGE 3
#define GEMM_SMEM (NSTAGE * STAGE_BYTES)     // 98304

// q scale: hd^-0.5 * log2(e), so softmax can run in exp2 domain
#define QSCALE (0.125f * 1.4426950408889634f)

__device__ __forceinline__ uint32_t a_addr(uint32_t tb, int m0, int ks, int lane) {
    int row = m0 + (lane & 15);
    int p = row >> 1;
    int chl = ((row & 1) << 2) | (ks << 1) | (lane >> 4);
    return tb + p * 128 + ((chl ^ (p & 7)) << 4);
}
__device__ __forceinline__ uint32_t b_addr(uint32_t tb, int n0, int ks, int lane) {
    int row = n0 + (lane & 7) + ((lane >> 4) << 3);
    int p = row >> 1;
    int chl = ((row & 1) << 2) | (ks << 1) | ((lane >> 3) & 1);
    return tb + p * 128 + ((chl ^ (p & 7)) << 4);
}

__global__ __launch_bounds__(256, 2) void gemm_mma_bf16x3(
    const __nv_bfloat16* __restrict__ Ah, const __nv_bfloat16* __restrict__ Al,
    const __nv_bfloat16* __restrict__ Bh, const __nv_bfloat16* __restrict__ Bl,
    const float* __restrict__ bias, float* __restrict__ C, int Nld, int mode,
    __nv_bfloat16* __restrict__ oqh, __nv_bfloat16* __restrict__ oql,
    __nv_bfloat16* __restrict__ okh, __nv_bfloat16* __restrict__ okl,
    __nv_bfloat16* __restrict__ ovh, __nv_bfloat16* __restrict__ ovl)
{
    extern __shared__ __align__(1024) char smraw[];
    const uint32_t sbase = smem_u32(smraw);
    const int tid = threadIdx.x;
    const int lane = tid & 31;
    const int wid = tid >> 5;
    const int wm = wid & 1;
    const int wn = wid >> 1;
    const int row0 = blockIdx.y * GBM;
    const int col0 = blockIdx.x * GBN;

    const int frow = tid >> 2;
    const int fkc  = tid & 3;
    uint32_t so0, so1;
    {
        int p0 = frow >> 1;
        int c0 = (((frow & 1) << 2) | fkc) ^ (p0 & 7);
        so0 = (uint32_t)(p0 * 128 + c0 * 16);
        int r1 = frow + 64;
        int p1 = r1 >> 1;
        int c1 = (((r1 & 1) << 2) | fkc) ^ (p1 & 7);
        so1 = (uint32_t)(p1 * 128 + c1 * 16);
    }
    const __nv_bfloat16* fs0 = Ah + (size_t)(row0 + frow) * KDIM + fkc * 8;
    const __nv_bfloat16* fs1 = Al + (size_t)(row0 + frow) * KDIM + fkc * 8;
    const __nv_bfloat16* fs2 = Bh + (size_t)(col0 + frow) * KDIM + fkc * 8;
    const __nv_bfloat16* fs3 = Bl + (size_t)(col0 + frow) * KDIM + fkc * 8;
    const size_t rstep = (size_t)64 * KDIM;

    float acc[4][4][4];
#pragma unroll
    for (int mi = 0; mi < 4; mi++)
#pragma unroll
        for (int ni = 0; ni < 4; ni++)
#pragma unroll
            for (int q = 0; q < 4; q++) acc[mi][ni][q] = 0.0f;

    auto fill = [&](int s) {
        uint32_t stg = sbase + s * STAGE_BYTES;
        CP16(stg + so0, fs0);                  CP16(stg + so1, fs0 + rstep);
        CP16(stg + TILE_BYTES + so0, fs1);     CP16(stg + TILE_BYTES + so1, fs1 + rstep);
        CP16(stg + 2 * TILE_BYTES + so0, fs2); CP16(stg + 2 * TILE_BYTES + so1, fs2 + rstep);
        CP16(stg + 3 * TILE_BYTES + so0, fs3); CP16(stg + 3 * TILE_BYTES + so1, fs3 + rstep);
        fs0 += GBK; fs1 += GBK; fs2 += GBK; fs3 += GBK;
        CP_COMMIT();
    };

    fill(0);
    fill(1);

    const int NCH = KDIM / GBK;   // 32
    for (int c = 0; c < NCH; c++) {
        int s = c % 3;
        if (c + 2 < NCH) { CP_WAIT(1); } else { CP_WAIT(0); }
        __syncthreads();
        if (c + 2 < NCH) fill((c + 2) % 3);

        uint32_t st = sbase + s * STAGE_BYTES;
#pragma unroll
        for (int ks = 0; ks < 2; ks++) {
            uint32_t aH[4][4], aL[4][4];
#pragma unroll
            for (int mi = 0; mi < 4; mi++) {
                ldsm4(aH[mi], a_addr(st,              wm * 64 + mi * 16, ks, lane));
                ldsm4(aL[mi], a_addr(st + TILE_BYTES, wm * 64 + mi * 16, ks, lane));
            }
#pragma unroll
            for (int g = 0; g < 2; g++) {
                uint32_t bh[4], bl[4];
                ldsm4(bh, b_addr(st + 2 * TILE_BYTES, wn * 32 + g * 16, ks, lane));
                ldsm4(bl, b_addr(st + 3 * TILE_BYTES, wn * 32 + g * 16, ks, lane));
#pragma unroll
                for (int mi = 0; mi < 4; mi++) {
                    mma16816(acc[mi][2 * g],     aH[mi], &bh[0]);
                    mma16816(acc[mi][2 * g + 1], aH[mi], &bh[2]);
                }
#pragma unroll
                for (int mi = 0; mi < 4; mi++) {
                    mma16816(acc[mi][2 * g],     aH[mi], &bl[0]);
                    mma16816(acc[mi][2 * g + 1], aH[mi], &bl[2]);
                }
#pragma unroll
                for (int mi = 0; mi < 4; mi++) {
                    mma16816(acc[mi][2 * g],     aL[mi], &bh[0]);
                    mma16816(acc[mi][2 * g + 1], aL[mi], &bh[2]);
                }
            }
        }
    }

    const int qr = lane >> 2, qc = lane & 3;
    if (mode == 0) {
#pragma unroll
        for (int mi = 0; mi < 4; mi++)
#pragma unroll
            for (int ni = 0; ni < 4; ni++) {
                int row = row0 + wm * 64 + mi * 16 + qr;
                int col = col0 + wn * 32 + ni * 8 + qc * 2;
                float2 bv = *(const float2*)(bias + col);
                float2 v0, v1;
                v0.x = acc[mi][ni][0] + bv.x;  v0.y = acc[mi][ni][1] + bv.y;
                v1.x = acc[mi][ni][2] + bv.x;  v1.y = acc[mi][ni][3] + bv.y;
                *(float2*)(C + (size_t)row * Nld + col) = v0;
                *(float2*)(C + (size_t)(row + 8) * Nld + col) = v1;
            }
    } else {
        int t = col0 >> 10;
        __nv_bfloat16* oh = (t == 0) ? oqh : (t == 1) ? okh : ovh;
        __nv_bfloat16* ol = (t == 0) ? oql : (t == 1) ? okl : ovl;
        float sc = (t == 0) ? QSCALE : 1.0f;   // q in exp2 domain
#pragma unroll
        for (int mi = 0; mi < 4; mi++)
#pragma unroll
            for (int ni = 0; ni < 4; ni++) {
                int row = row0 + wm * 64 + mi * 16 + qr;
                int gcol = col0 + wn * 32 + ni * 8 + qc * 2;
                int lcol = gcol & 1023;
                float2 bv = *(const float2*)(bias + gcol);
                float x0 = (acc[mi][ni][0] + bv.x) * sc;
                float x1 = (acc[mi][ni][1] + bv.y) * sc;
                float x2 = (acc[mi][ni][2] + bv.x) * sc;
                float x3 = (acc[mi][ni][3] + bv.y) * sc;
                __nv_bfloat16 h0 = __float2bfloat16(x0), h1 = __float2bfloat16(x1);
                __nv_bfloat16 h2 = __float2bfloat16(x2), h3 = __float2bfloat16(x3);
                size_t i0 = (size_t)row * DD + lcol;
                size_t i1 = (size_t)(row + 8) * DD + lcol;
                *(__nv_bfloat162*)(oh + i0) = __halves2bfloat162(h0, h1);
                *(__nv_bfloat162*)(oh + i1) = __halves2bfloat162(h2, h3);
                *(__nv_bfloat162*)(ol + i0) = __floats2bfloat162_rn(
                    x0 - __bfloat162float(h0), x1 - __bfloat162float(h1));
                *(__nv_bfloat162*)(ol + i1) = __floats2bfloat162_rn(
                    x2 - __bfloat162float(h2), x3 - __bfloat162float(h3));
            }
    }
}

// ---------------------------------------------------------------------------
// Flash attention, mma.sync bf16x3, causal — R12 structure (128-thread CTAs,
// 64-row Q tile, 128-row KV single-buffered, 2 CTAs/SM) with LPT scheduling:
// largest q-tiles (most KV work) launch first.
// ---------------------------------------------------------------------------
#define ATT_Q_B 8192                           // 64 rows x 128 B
#define ATT_KV_T 16384                         // 128 rows x 128 B per tensor
#define ATT_SMEM (2 * ATT_Q_B + 4 * ATT_KV_T)  // 81920

__device__ __forceinline__ uint32_t sw128(uint32_t tb, int row, int chunk) {
    return tb + row * 128 + ((chunk ^ (row & 7)) << 4);
}
__device__ __forceinline__ uint32_t fa_a(uint32_t tb, int m0, int ks, int lane) {
    int row = m0 + (lane & 15);
    return sw128(tb, row, ks * 2 + (lane >> 4));
}
__device__ __forceinline__ uint32_t fa_b(uint32_t tb, int n0, int ks, int lane) {
    int row = n0 + (lane & 7) + ((lane >> 4) << 3);
    return sw128(tb, row, ks * 2 + ((lane >> 3) & 1));
}
__device__ __forceinline__ uint32_t fa_v(uint32_t tb, int kv0, int hd0, int lane) {
    int row = kv0 + (((lane >> 3) & 1) << 3) + (lane & 7);
    return sw128(tb, row, (hd0 >> 3) + (lane >> 4));
}

__global__ __launch_bounds__(128, 2) void flash_attn_mma(
    const __nv_bfloat16* __restrict__ qh, const __nv_bfloat16* __restrict__ ql,
    const __nv_bfloat16* __restrict__ kh, const __nv_bfloat16* __restrict__ kl,
    const __nv_bfloat16* __restrict__ vh, const __nv_bfloat16* __restrict__ vl,
    __nv_bfloat16* __restrict__ yh, __nv_bfloat16* __restrict__ yl)
{
    extern __shared__ __align__(1024) char smraw[];
    const uint32_t sb = smem_u32(smraw);
    // LPT: heaviest q-tiles first
    const int qt = (SS / 64 - 1) - blockIdx.x;
    const int h = blockIdx.y, b = blockIdx.z;
    const int tid = threadIdx.x, lane = tid & 31, w = tid >> 5;   // w in 0..3
    const size_t rowbase = (size_t)(b * SS) + qt * 64;
    const int hoff = h * HDIM;

    const uint32_t sQh = sb, sQl = sb + ATT_Q_B;
    const uint32_t tKh = sb + 2 * ATT_Q_B;
    const uint32_t tKl = tKh + ATT_KV_T;
    const uint32_t tVh = tKh + 2 * ATT_KV_T;
    const uint32_t tVl = tKh + 3 * ATT_KV_T;

    // one-time Q load (64 rows x 64 cols, hi+lo) — completes with first CP_WAIT
    {
        const __nv_bfloat16* qs[2] = {qh, ql};
        for (int i = tid; i < 1024; i += 128) {
            int t = i >> 9, idx = i & 511, r = idx >> 3, ch = idx & 7;
            CP16(sw128(t ? sQl : sQh, r, ch),
                 qs[t] + (rowbase + r) * DD + hoff + ch * 8);
        }
        CP_COMMIT();
    }

    const __nv_bfloat16* kvs[4] = {kh, kl, vh, vl};
    auto fillkv = [&](int kt) {
        size_t kvrow = (size_t)(b * SS) + (size_t)kt * 128;
        for (int i = tid; i < 4096; i += 128) {
            int t = i >> 10, idx = i & 1023, r = idx >> 3, ch = idx & 7;
            CP16(sw128(tKh + t * ATT_KV_T, r, ch),
                 kvs[t] + (kvrow + r) * DD + hoff + ch * 8);
        }
        CP_COMMIT();
    };

    float o[8][4];
#pragma unroll
    for (int i = 0; i < 8; i++)
#pragma unroll
        for (int q = 0; q < 4; q++) o[i][q] = 0.0f;
    float mrow[2] = {-1e30f, -1e30f};
    float lrow[2] = {0.0f, 0.0f};

    uint32_t aQh[4][4], aQl[4][4];
    const int qr = lane >> 2, qc = lane & 3;

    const int nkt = (qt + 2) >> 1;   // ceil((qt+1)*64 / 128)

    for (int kt = 0; kt < nkt; kt++) {
        fillkv(kt);
        CP_WAIT(0);
        __syncthreads();

        if (kt == 0) {
#pragma unroll
            for (int ks = 0; ks < 4; ks++) {
                ldsm4(aQh[ks], fa_a(sQh, w * 16, ks, lane));
                ldsm4(aQl[ks], fa_a(sQl, w * 16, ks, lane));
            }
        }

        // ---- S = Q @ K^T ----
        float sfr[16][4];
#pragma unroll
        for (int i = 0; i < 16; i++)
#pragma unroll
            for (int q = 0; q < 4; q++) sfr[i][q] = 0.0f;

#pragma unroll
        for (int ks = 0; ks < 4; ks++)
#pragma unroll
            for (int np = 0; np < 4; np++) {
                int ng0 = 2 * np, ng1 = 2 * np + 1;
                uint32_t bhA[4], blA[4], bhB[4], blB[4];
                ldsm4(bhA, fa_b(tKh, ng0 * 16, ks, lane));
                ldsm4(blA, fa_b(tKl, ng0 * 16, ks, lane));
                ldsm4(bhB, fa_b(tKh, ng1 * 16, ks, lane));
                ldsm4(blB, fa_b(tKl, ng1 * 16, ks, lane));
                mma16816(sfr[2 * ng0],     aQh[ks], &bhA[0]);
                mma16816(sfr[2 * ng0 + 1], aQh[ks], &bhA[2]);
                mma16816(sfr[2 * ng1],     aQh[ks], &bhB[0]);
                mma16816(sfr[2 * ng1 + 1], aQh[ks], &bhB[2]);
                mma16816(sfr[2 * ng0],     aQh[ks], &blA[0]);
                mma16816(sfr[2 * ng0 + 1], aQh[ks], &blA[2]);
                mma16816(sfr[2 * ng1],     aQh[ks], &blB[0]);
                mma16816(sfr[2 * ng1 + 1], aQh[ks], &blB[2]);
                mma16816(sfr[2 * ng0],     aQl[ks], &bhA[0]);
                mma16816(sfr[2 * ng0 + 1], aQl[ks], &bhA[2]);
                mma16816(sfr[2 * ng1],     aQl[ks], &bhB[0]);
                mma16816(sfr[2 * ng1 + 1], aQl[ks], &bhB[2]);
            }

        // ---- causal mask (only the last KV tile overlaps the diagonal) ----
        if (kt == nkt - 1) {
            int r0 = w * 16 + qr;               // q row within tile (0..63)
            int cbase = kt * 128 - qt * 64;     // KV col offset rel. to q rows
#pragma unroll
            for (int nf = 0; nf < 16; nf++) {
                int c0 = cbase + nf * 8 + qc * 2;
                if (c0 > r0)     sfr[nf][0] = -1e30f;
                if (c0 + 1 > r0) sfr[nf][1] = -1e30f;
                if (c0 > r0 + 8)     sfr[nf][2] = -1e30f;
                if (c0 + 1 > r0 + 8) sfr[nf][3] = -1e30f;
            }
        }

        // ---- online softmax ----
        float tm0 = -1e30f, tm1 = -1e30f;
#pragma unroll
        for (int nf = 0; nf < 16; nf++) {
            tm0 = fmaxf(tm0, fmaxf(sfr[nf][0], sfr[nf][1]));
            tm1 = fmaxf(tm1, fmaxf(sfr[nf][2], sfr[nf][3]));
        }
#pragma unroll
        for (int off = 1; off <= 2; off <<= 1) {
            tm0 = fmaxf(tm0, __shfl_xor_sync(0xffffffffu, tm0, off));
            tm1 = fmaxf(tm1, __shfl_xor_sync(0xffffffffu, tm1, off));
        }
        float mn0 = fmaxf(mrow[0], tm0), mn1 = fmaxf(mrow[1], tm1);
        float al0 = exp2f(mrow[0] - mn0), al1 = exp2f(mrow[1] - mn1);
        mrow[0] = mn0; mrow[1] = mn1;
#pragma unroll
        for (int i = 0; i < 8; i++) {
            o[i][0] *= al0; o[i][1] *= al0;
            o[i][2] *= al1; o[i][3] *= al1;
        }

        float rs0 = 0.0f, rs1 = 0.0f;
#pragma unroll
        for (int nf = 0; nf < 16; nf++) {
            sfr[nf][0] = exp2f(sfr[nf][0] - mn0);
            sfr[nf][1] = exp2f(sfr[nf][1] - mn0);
            sfr[nf][2] = exp2f(sfr[nf][2] - mn1);
            sfr[nf][3] = exp2f(sfr[nf][3] - mn1);
            rs0 += sfr[nf][0] + sfr[nf][1];
            rs1 += sfr[nf][2] + sfr[nf][3];
        }

        // ---- O += P @ V ----
#pragma unroll
        for (int ks = 0; ks < 8; ks++) {
            const float* f0 = sfr[2 * ks];
            const float* f1 = sfr[2 * ks + 1];
            uint32_t phx[4], plx[4];
            phx[0] = pack_bf2(f0[0], f0[1]);
            phx[1] = pack_bf2(f0[2], f0[3]);
            phx[2] = pack_bf2(f1[0], f1[1]);
            phx[3] = pack_bf2(f1[2], f1[3]);
            {
                __nv_bfloat162 h0 = *(__nv_bfloat162*)&phx[0];
                __nv_bfloat162 h1 = *(__nv_bfloat162*)&phx[1];
                __nv_bfloat162 h2 = *(__nv_bfloat162*)&phx[2];
                __nv_bfloat162 h3 = *(__nv_bfloat162*)&phx[3];
                plx[0] = pack_bf2(f0[0] - __bfloat162float(h0.x), f0[1] - __bfloat162float(h0.y));
                plx[1] = pack_bf2(f0[2] - __bfloat162float(h1.x), f0[3] - __bfloat162float(h1.y));
                plx[2] = pack_bf2(f1[0] - __bfloat162float(h2.x), f1[1] - __bfloat162float(h2.y));
                plx[3] = pack_bf2(f1[2] - __bfloat162float(h3.x), f1[3] - __bfloat162float(h3.y));
            }
#pragma unroll
            for (int gp = 0; gp < 2; gp++) {
                int ng0 = 2 * gp, ng1 = 2 * gp + 1;
                uint32_t vhA[4], vlA[4], vhB[4], vlB[4];
                ldsm4t(vhA, fa_v(tVh, ks * 16, ng0 * 16, lane));
                ldsm4t(vlA, fa_v(tVl, ks * 16, ng0 * 16, lane));
                ldsm4t(vhB, fa_v(tVh, ks * 16, ng1 * 16, lane));
                ldsm4t(vlB, fa_v(tVl, ks * 16, ng1 * 16, lane));
                mma16816(o[2 * ng0],     phx, &vhA[0]);
                mma16816(o[2 * ng0 + 1], phx, &vhA[2]);
                mma16816(o[2 * ng1],     phx, &vhB[0]);
                mma16816(o[2 * ng1 + 1], phx, &vhB[2]);
                mma16816(o[2 * ng0],     plx, &vhA[0]);
                mma16816(o[2 * ng0 + 1], plx, &vhA[2]);
                mma16816(o[2 * ng1],     plx, &vhB[0]);
                mma16816(o[2 * ng1 + 1], plx, &vhB[2]);
                mma16816(o[2 * ng0],     phx, &vlA[0]);
                mma16816(o[2 * ng0 + 1], phx, &vlA[2]);
                mma16816(o[2 * ng1],     phx, &vlB[0]);
                mma16816(o[2 * ng1 + 1], phx, &vlB[2]);
            }
        }

        // deferred row-sum reduction (off the tensor critical path)
#pragma unroll
        for (int off = 1; off <= 2; off <<= 1) {
            rs0 += __shfl_xor_sync(0xffffffffu, rs0, off);
            rs1 += __shfl_xor_sync(0xffffffffu, rs1, off);
        }
        lrow[0] = lrow[0] * al0 + rs0;
        lrow[1] = lrow[1] * al1 + rs1;

        __syncthreads();   // all warps done reading KV before next overwrite
    }

    // ---- epilogue: O/l -> yh/yl ----
    float inv0 = 1.0f / lrow[0];
    float inv1 = 1.0f / lrow[1];
    size_t r0 = rowbase + w * 16 + qr;
#pragma unroll
    for (int i = 0; i < 8; i++) {
        int col = hoff + i * 8 + qc * 2;
        float x0 = o[i][0] * inv0, x1 = o[i][1] * inv0;
        float x2 = o[i][2] * inv1, x3 = o[i][3] * inv1;
        __nv_bfloat16 h0 = __float2bfloat16(x0), h1 = __float2bfloat16(x1);
        __nv_bfloat16 h2 = __float2bfloat16(x2), h3 = __float2bfloat16(x3);
        size_t i0 = r0 * DD + col;
        size_t i1 = (r0 + 8) * DD + col;
        *(__nv_bfloat162*)(yh + i0) = __halves2bfloat162(h0, h1);
        *(__nv_bfloat162*)(yh + i1) = __halves2bfloat162(h2, h3);
        *(__nv_bfloat162*)(yl + i0) = __floats2bfloat162_rn(
            x0 - __bfloat162float(h0), x1 - __bfloat162float(h1));
        *(__nv_bfloat162*)(yl + i1) = __floats2bfloat162_rn(
            x2 - __bfloat162float(h2), x3 - __bfloat162float(h3));
    }
}

// ---------------------------------------------------------------------------
extern "C" void kernel_launch(void* const* d_in, const int* in_sizes, int n_in,
                              void* d_out, int out_size)
{
    const float* x      = (const float*)d_in[0];
    const float* W_attn = (const float*)d_in[1];
    const float* b_attn = (const float*)d_in[2];
    const float* W_proj = (const float*)d_in[3];
    const float* b_proj = (const float*)d_in[4];
    float* out = (float*)d_out;

    __nv_bfloat16 *xh, *xl, *qhp, *qlp, *khp, *klp, *vhp, *vlp, *yhp, *ylp;
    __nv_bfloat16 *wah, *wal, *wph, *wpl;
    cudaGetSymbolAddress((void**)&xh,  g_xh);
    cudaGetSymbolAddress((void**)&xl,  g_xl);
    cudaGetSymbolAddress((void**)&qhp, g_qh);
    cudaGetSymbolAddress((void**)&qlp, g_ql);
    cudaGetSymbolAddress((void**)&khp, g_kh);
    cudaGetSymbolAddress((void**)&klp, g_kl);
    cudaGetSymbolAddress((void**)&vhp, g_vh);
    cudaGetSymbolAddress((void**)&vlp, g_vl);
    cudaGetSymbolAddress((void**)&yhp, g_yh);
    cudaGetSymbolAddress((void**)&ylp, g_yl);
    cudaGetSymbolAddress((void**)&wah, g_wah);
    cudaGetSymbolAddress((void**)&wal, g_wal);
    cudaGetSymbolAddress((void**)&wph, g_wph);
    cudaGetSymbolAddress((void**)&wpl, g_wpl);

    cudaFuncSetAttribute(gemm_mma_bf16x3, cudaFuncAttributeMaxDynamicSharedMemorySize,
                         (int)GEMM_SMEM);
    cudaFuncSetAttribute(flash_attn_mma, cudaFuncAttributeMaxDynamicSharedMemorySize,
                         (int)ATT_SMEM);

    // fused prep: x split + both weight transpose-splits in one launch
    prep_fused<<<XB + 4096, 256>>>(x, xh, xl, W_attn, wah, wal, W_proj, wph, wpl);

    gemm_mma_bf16x3<<<dim3(3 * DD / GBN, MROWS / GBM), 256, GEMM_SMEM>>>(
        xh, xl, wah, wal, b_attn, nullptr, 3 * DD, 1,
        qhp, qlp, khp, klp, vhp, vlp);

    flash_attn_mma<<<dim3(SS / 64, HH, BB), 128, ATT_SMEM>>>(
        qhp, qlp, khp, klp, vhp, vlp, yhp, ylp);

    gemm_mma_bf16x3<<<dim3(DD / GBN, MROWS / GBM), 256, GEMM_SMEM>>>(
        yhp, ylp, wph, wpl, b_proj, out, DD, 0,
        nullptr, nullptr, nullptr, nullptr, nullptr, nullptr);
}